// round 12
// baseline (speedup 1.0000x reference)
#include <cuda_runtime.h>
#include <cuda_fp16.h>
#include <math.h>
#include <stdint.h>

#define B_  8
#define C_  256
#define T_  8
#define H_  56
#define W_  56
#define HW_ (H_*W_)
#define CR_ 64
#define PR_ 58
#define PC_ 64
#define PXI_ (PR_*PC_)     // 3712
#define NIMG 64
#define APH 40             // smem row pitch in halves (80B) — LDSM conflict-free
#define ABUFH (258*APH)
#define BBUFH (256*APH)
#define EPS 132
#define SMEM_BYTES (1024 + 2*ABUFH*2 + 4*BBUFH*2)   // 124224

__device__ float  g_pool[B_*C_*T_];
__device__ float  g_walpha[B_*C_*T_];
__device__ float  g_balpha[B_*C_*T_];
__device__ float  g_conv[(size_t)B_*C_*T_*HW_];
__device__ double g_stats[C_][4];
__device__ __half g_xs[(size_t)NIMG*PXI_*C_ + 4096]; // padded NHWC fp16 (+OOB guard)
__device__ __half g_wp[9*8*256*32];                  // [tap][kc][o][cc] fp16 (fragment-linear)

// ---------------- helpers ----------------
__device__ __forceinline__ uint32_t smem_to_u32(const void* p) {
    uint32_t a;
    asm("{ .reg .u64 t; cvta.to.shared.u64 t, %1; cvt.u32.u64 %0, t; }" : "=r"(a) : "l"(p));
    return a;
}
__device__ __forceinline__ void cp_async16(uint32_t dst, const void* src) {
    asm volatile("cp.async.ca.shared.global [%0], [%1], 16;" :: "r"(dst), "l"(src));
}
#define CP_COMMIT()   asm volatile("cp.async.commit_group;" ::: "memory")
#define CP_WAIT_ALL() asm volatile("cp.async.wait_all;" ::: "memory")
#define CP_WAIT0()    asm volatile("cp.async.wait_group 0;" ::: "memory")

__device__ __forceinline__ void mma_f16(float* c, const uint32_t* a, uint32_t b0, uint32_t b1) {
    asm volatile("mma.sync.aligned.m16n8k16.row.col.f32.f16.f16.f32 "
        "{%0,%1,%2,%3}, {%4,%5,%6,%7}, {%8,%9}, {%0,%1,%2,%3};"
        : "+f"(c[0]), "+f"(c[1]), "+f"(c[2]), "+f"(c[3])
        : "r"(a[0]), "r"(a[1]), "r"(a[2]), "r"(a[3]), "r"(b0), "r"(b1));
}
__device__ __forceinline__ void ldsm4(uint32_t* r, uint32_t addr) {
    asm volatile("ldmatrix.sync.aligned.m8n8.x4.shared.b16 {%0,%1,%2,%3}, [%4];"
        : "=r"(r[0]), "=r"(r[1]), "=r"(r[2]), "=r"(r[3]) : "r"(addr));
}
__device__ __forceinline__ float qgelu(float x) { return x / (1.f + __expf(-1.702f * x)); }

// ---------------- pool ----------------
__global__ void pool_kernel(const float* __restrict__ feat) {
    int bct = blockIdx.x;
    const float* p = feat + (size_t)bct * HW_;
    float s = 0.f;
    for (int i = threadIdx.x; i < HW_; i += blockDim.x) s += p[i];
    for (int o = 16; o; o >>= 1) s += __shfl_down_sync(0xffffffffu, s, o);
    __shared__ float sb[8];
    int lane = threadIdx.x & 31, w = threadIdx.x >> 5;
    if (lane == 0) sb[w] = s;
    __syncthreads();
    if (threadIdx.x == 0) {
        float t = 0.f;
        for (int i = 0; i < (int)(blockDim.x >> 5); i++) t += sb[i];
        g_pool[bct] = t * (1.f / HW_);
    }
}

// ---------------- routing + weight-prepack + stats-zero (fused grid) ----------------
__global__ void routing_fused_kernel(
    const float* __restrict__ a_w, const float* __restrict__ a_b,
    const float* __restrict__ norm_w, const float* __restrict__ norm_b,
    const float* __restrict__ normt_w, const float* __restrict__ normt_b,
    const float* __restrict__ qkv_w, const float* __restrict__ qkv_b,
    const float* __restrict__ ao_w, const float* __restrict__ ao_b,
    const float* __restrict__ b_w, const float* __restrict__ bb_w,
    const float* __restrict__ Wt)
{
    int tid = threadIdx.x;
    if (blockIdx.x >= B_) {
        int pb = blockIdx.x - B_;
        if (pb == 0) {
            for (int i = tid; i < C_*4; i += 256) ((double*)g_stats)[i] = 0.0;
        }
        int idx = pb * 256 + tid;           // < 589824
        int cc = idx & 31, o = (idx >> 5) & 255, kc = (idx >> 13) & 7, tap = idx >> 16;
        int ky = tap / 3, kx = tap % 3;
        g_wp[idx] = __float2half_rn(Wt[(((size_t)o*C_ + kc*32 + cc)*3 + ky)*3 + kx]);
        return;
    }
    int b = blockIdx.x;
    __shared__ float s_pool[C_][T_], s_x1[CR_][T_], s_x2[CR_][T_], s_xn[CR_][T_];
    __shared__ float s_qkv[3*CR_][T_], s_att[T_][T_], s_o[CR_][T_], s_mu[T_], s_rstd[T_];

    for (int i = tid; i < C_*T_; i += 256) s_pool[i >> 3][i & 7] = g_pool[b*C_*T_ + i];
    __syncthreads();
    for (int idx = tid; idx < CR_*T_; idx += 256) {
        int r = idx >> 3, t = idx & 7;
        float acc = a_b[r];
        const float* wb = a_w + (size_t)r * C_ * 3;
        for (int c = 0; c < C_; c++) {
            float p0 = (t > 0) ? s_pool[c][t-1] : 0.f, p1 = s_pool[c][t], p2 = (t < 7) ? s_pool[c][t+1] : 0.f;
            const float* w = wb + c*3;
            acc += w[0]*p0 + w[1]*p1 + w[2]*p2;
        }
        s_x1[r][t] = acc;
    }
    __syncthreads();
    if (tid < T_) {
        int t = tid;
        float mu = 0.f;
        for (int r = 0; r < CR_; r++) mu += s_x1[r][t];
        mu *= (1.f / CR_);
        float v = 0.f;
        for (int r = 0; r < CR_; r++) { float d = s_x1[r][t] - mu; v += d*d; }
        s_mu[t] = mu; s_rstd[t] = rsqrtf(v * (1.f / CR_) + 1e-6f);
    }
    __syncthreads();
    for (int idx = tid; idx < CR_*T_; idx += 256) {
        int r = idx >> 3, t = idx & 7;
        s_x2[r][t] = qgelu((s_x1[r][t] - s_mu[t]) * s_rstd[t] * norm_w[r] + norm_b[r]);
    }
    __syncthreads();
    if (tid < T_) {
        int t = tid;
        float mu = 0.f;
        for (int r = 0; r < CR_; r++) mu += s_x2[r][t];
        mu *= (1.f / CR_);
        float v = 0.f;
        for (int r = 0; r < CR_; r++) { float d = s_x2[r][t] - mu; v += d*d; }
        s_mu[t] = mu; s_rstd[t] = rsqrtf(v * (1.f / CR_) + 1e-6f);
    }
    __syncthreads();
    for (int idx = tid; idx < CR_*T_; idx += 256) {
        int r = idx >> 3, t = idx & 7;
        s_xn[r][t] = (s_x2[r][t] - s_mu[t]) * s_rstd[t] * normt_w[r] + normt_b[r];
    }
    __syncthreads();
    for (int idx = tid; idx < 3*CR_*T_; idx += 256) {
        int o = idx >> 3, t = idx & 7;
        float acc = qkv_b[o];
        const float* w = qkv_w + (size_t)o * CR_;
        for (int c = 0; c < CR_; c++) acc += w[c] * s_xn[c][t];
        s_qkv[o][t] = acc;
    }
    __syncthreads();
    if (tid < T_*T_) {
        int i = tid >> 3, j = tid & 7;
        float a = 0.f;
        for (int d = 0; d < CR_; d++) a += s_qkv[d][i] * s_qkv[CR_ + d][j];
        s_att[i][j] = a * 0.125f;
    }
    __syncthreads();
    if (tid < T_) {
        int i = tid;
        float m = -1e30f;
        for (int j = 0; j < T_; j++) m = fmaxf(m, s_att[i][j]);
        float sum = 0.f;
        for (int j = 0; j < T_; j++) { float e = __expf(s_att[i][j] - m); s_att[i][j] = e; sum += e; }
        float inv = 1.f / sum;
        for (int j = 0; j < T_; j++) s_att[i][j] *= inv;
    }
    __syncthreads();
    for (int idx = tid; idx < CR_*T_; idx += 256) {
        int d = idx >> 3, t = idx & 7;
        float a = 0.f;
        for (int j = 0; j < T_; j++) a += s_att[t][j] * s_qkv[2*CR_ + d][j];
        s_o[d][t] = a;
    }
    __syncthreads();
    for (int idx = tid; idx < CR_*T_; idx += 256) {
        int r = idx >> 3, t = idx & 7;
        float acc = ao_b[r];
        const float* w = ao_w + (size_t)r * CR_;
        for (int c = 0; c < CR_; c++) acc += w[c] * s_o[c][t];
        s_x1[r][t] = s_x2[r][t] + acc;
    }
    __syncthreads();
    for (int idx = tid; idx < C_*T_; idx += 256) {
        int Co = idx >> 3, t = idx & 7;
        float aw = 0.f, ab = 0.f;
        const float* w1b = b_w  + (size_t)Co * CR_ * 3;
        const float* w2b = bb_w + (size_t)Co * CR_ * 3;
        for (int r = 0; r < CR_; r++) {
            float x0 = (t > 0) ? s_x1[r][t-1] : 0.f, x1 = s_x1[r][t], x2 = (t < 7) ? s_x1[r][t+1] : 0.f;
            const float* w1 = w1b + r*3;
            const float* w2 = w2b + r*3;
            aw += w1[0]*x0 + w1[1]*x1 + w1[2]*x2;
            ab += w2[0]*x0 + w2[1]*x1 + w2[2]*x2;
        }
        g_walpha[b*C_*T_ + idx] = aw;
        g_balpha[b*C_*T_ + idx] = ab;
    }
}

// ---- stage scaled input -> padded NHWC fp16 ----
__global__ void stage_xs_kernel(const float* __restrict__ feat) {
    __shared__ float s[32][65];
    int img = blockIdx.z, r = blockIdx.y, c0 = blockIdx.x * 32;
    int b = img >> 3, t = img & 7;
    int tid = threadIdx.x;
    int x = tid & 63, cl0 = tid >> 6;
    for (int cl = cl0; cl < 32; cl += 4) {
        float v = 0.f;
        if (r >= 1 && r <= 56 && x >= 1 && x <= 56) {
            int c = c0 + cl;
            v = feat[(((size_t)(b*C_ + c))*T_ + t)*HW_ + (r-1)*W_ + (x-1)] * g_walpha[(b*C_ + c)*T_ + t];
        }
        s[cl][x] = v;
    }
    __syncthreads();
    int k = tid & 31, x0 = tid >> 5;
    for (int xx = x0; xx < 64; xx += 8)
        g_xs[((size_t)img*PXI_ + r*PC_ + xx)*C_ + c0 + k] = __float2half_rn(s[k][xx]);
}

// ---------------- conv: implicit GEMM fp16; B via LDG.128 register pipeline ----------------
__global__ void __launch_bounds__(256, 1)
conv_mma_kernel(const float* __restrict__ bias_p)
{
    extern __shared__ char smc[];
    float*  bias_sm = (float*)smc;
    __half* As = (__half*)(smc + 1024);       // 2 x ABUFH halves
    __half* Bs = As + 2*ABUFH;                // 4 x BBUFH halves (ring)
    uint32_t as_u = smem_to_u32(As);
    uint32_t bs_u = smem_to_u32(Bs);

    int tid = threadIdx.x, lane = tid & 31, wid = tid >> 5;
    int wm = wid >> 2, wn = wid & 3;          // warps 2(M) x 4(N)
    int mg = lane >> 2, tg = lane & 3;
    int img = blockIdx.y, yt = blockIdx.x;
    int b = img >> 3, t = img & 7;
    size_t imgP = (size_t)img * PXI_ + (size_t)yt * 128;

    // per-lane ldmatrix address offsets (bytes)
    uint32_t aoff_l = (uint32_t)((((lane & 7) + (lane & 8)) * APH + ((lane & 16) >> 1)) * 2);
    uint32_t boff_l = (uint32_t)((((lane & 7) + ((lane & 16) >> 1)) * APH + (lane & 8)) * 2);

    // per-thread B staging addresses (fragment-linear prepack)
    uint32_t bsts_off = (uint32_t)((tid >> 2)*80 + (tid & 3)*16);   // within a B buffer

    if (tid < 256) bias_sm[tid] = g_balpha[(b*C_ + tid)*T_ + t] * bias_p[tid];

    // preload A(kc=0) -> Abuf0, B tiles tt=0,1 -> ring bufs 0,1 (cp.async, startup only)
    const __half* srcA0 = g_xs + imgP*C_;
    for (int idx = tid; idx < 258*4; idx += 256) {
        int p = idx >> 2, q = idx & 3;
        cp_async16(as_u + (uint32_t)(p*80 + q*16), srcA0 + (size_t)p*C_ + q*8);
    }
    for (int idx = tid; idx < 2048; idx += 256) {
        int t0 = idx >> 10, r = idx & 1023;
        cp_async16(bs_u + (uint32_t)(t0*(BBUFH*2)) + (uint32_t)((r>>2)*80 + (r&3)*16),
                   g_wp + (size_t)((t0 % 9)*8 + t0/9)*8192 + r*8);
    }
    CP_COMMIT(); CP_WAIT_ALL();
    __syncthreads();

    float acc[4][8][4] = {};

    for (int tt = 0; tt < 72; tt++) {
        int kc = tt / 9, tap = tt % 9;
        bool pref = (tt + 2 < 72);
        int n = tt + 2;
        const uint4* wp4 = (const uint4*)(g_wp + (size_t)((n % 9)*8 + n/9)*8192);
        char* bdst = (char*)Bs + (uint32_t)((n & 3)*(BBUFH*2)) + bsts_off;
        uint4 br0, br1;
        if (pref) { br0 = __ldg(wp4 + tid); br1 = __ldg(wp4 + tid + 256); }

        // A(kc+1) slice prefetch (cp.async; flushed at kc boundary)
        if (kc < 7 && tap < 7) {
            const __half* srcAn = g_xs + imgP*C_ + (size_t)(kc+1)*32;
            uint32_t dsta = as_u + (uint32_t)(((kc+1) & 1)*(ABUFH*2));
            int r0 = tap*37, r1 = min(r0 + 37, 258);
            for (int idx = tid + r0*4; idx < r1*4; idx += 256) {
                int p = idx >> 2, q = idx & 3;
                cp_async16(dsta + (uint32_t)(p*80 + q*16), srcAn + (size_t)p*C_ + q*8);
            }
            CP_COMMIT();
        }

        int off = (tap/3)*64 + (tap%3);
        uint32_t abase = as_u + (uint32_t)((kc & 1)*(ABUFH*2)) + (uint32_t)((off + wm*64)*80) + aoff_l;
        uint32_t bbase = bs_u + (uint32_t)((tt & 3)*(BBUFH*2)) + (uint32_t)((wn*64)*80) + boff_l;

        // ---- ks = 0 ----
        {
            uint32_t af[4][4];
            #pragma unroll
            for (int i = 0; i < 4; i++)
                ldsm4(af[i], abase + (uint32_t)(i*16*80));
            #pragma unroll
            for (int jp = 0; jp < 4; jp++) {
                uint32_t bf[4];
                ldsm4(bf, bbase + (uint32_t)(jp*16*80));
                #pragma unroll
                for (int i = 0; i < 4; i++) {
                    mma_f16(acc[i][2*jp],   af[i], bf[0], bf[1]);
                    mma_f16(acc[i][2*jp+1], af[i], bf[2], bf[3]);
                }
            }
        }
        // store first half of B(tt+2), load second half
        if (pref) {
            *(uint4*)(bdst) = br0;
            *(uint4*)(bdst + 5120) = br1;
            br0 = __ldg(wp4 + tid + 512);
            br1 = __ldg(wp4 + tid + 768);
        }
        // ---- ks = 1 ----
        {
            uint32_t af[4][4];
            #pragma unroll
            for (int i = 0; i < 4; i++)
                ldsm4(af[i], abase + (uint32_t)(i*16*80 + 32));
            #pragma unroll
            for (int jp = 0; jp < 4; jp++) {
                uint32_t bf[4];
                ldsm4(bf, bbase + (uint32_t)(jp*16*80 + 32));
                #pragma unroll
                for (int i = 0; i < 4; i++) {
                    mma_f16(acc[i][2*jp],   af[i], bf[0], bf[1]);
                    mma_f16(acc[i][2*jp+1], af[i], bf[2], bf[3]);
                }
            }
        }
        if (pref) {
            *(uint4*)(bdst + 10240) = br0;
            *(uint4*)(bdst + 15360) = br1;
        }
        if (tap == 8) CP_WAIT0();    // flush A(kc+1) slices before buffer swap
        __syncthreads();
    }

    // epilogue: transpose through smem, coalesced float4 stores
    float* ep = (float*)(smc + 1024);   // 128 x EPS floats
    #pragma unroll
    for (int h = 0; h < 2; h++) {
        if ((wn >> 1) == h) {
            #pragma unroll
            for (int i = 0; i < 4; i++)
                #pragma unroll
                for (int j = 0; j < 8; j++)
                    #pragma unroll
                    for (int e = 0; e < 4; e++) {
                        int nl = (wn & 1)*64 + j*8 + tg*2 + (e & 1);
                        int m  = wm*64 + i*16 + mg + ((e >> 1)*8);
                        ep[nl*EPS + m] = acc[i][j][e] + bias_sm[h*128 + nl];
                    }
        }
        __syncthreads();
        int sub = lane >> 4, xi = lane & 15;
        #pragma unroll
        for (int it = 0; it < 16; it++) {
            int rowIdx = it*16 + wid*2 + sub;   // 0..255 = ch(128) x ry(2)
            int ch = rowIdx >> 1, ry = rowIdx & 1;
            if (xi < 14) {
                float4 v = *(const float4*)&ep[ch*EPS + ry*64 + xi*4];
                *(float4*)&g_conv[(((size_t)(b*C_ + h*128 + ch))*T_ + t)*HW_ + (yt*2 + ry)*W_ + xi*4] = v;
            }
        }
        __syncthreads();
    }
}

// ---------------- stats + final ----------------
__global__ void stats_kernel() {
    int c = blockIdx.y;
    int item = blockIdx.x * blockDim.x + threadIdx.x;
    int b = item / HW_, hw = item % HW_;
    size_t base = (((size_t)b*C_ + c)*T_) * HW_ + hw;
    float so = 0.f, sq = 0.f, sa = 0.f, sqa = 0.f, prev = 0.f, cur = g_conv[base];
    #pragma unroll
    for (int t = 0; t < T_; t++) {
        float nxt = (t < T_-1) ? g_conv[base + (size_t)(t+1)*HW_] : 0.f;
        so += cur; sq += cur*cur;
        float ap = (prev + cur + nxt) * (1.f/3.f);
        sa += ap; sqa += ap*ap;
        prev = cur; cur = nxt;
    }
    __shared__ float sb[4][8];
    for (int o = 16; o; o >>= 1) {
        so += __shfl_down_sync(0xffffffffu, so, o);
        sq += __shfl_down_sync(0xffffffffu, sq, o);
        sa += __shfl_down_sync(0xffffffffu, sa, o);
        sqa += __shfl_down_sync(0xffffffffu, sqa, o);
    }
    int lane = threadIdx.x & 31, w = threadIdx.x >> 5;
    if (lane == 0) { sb[0][w] = so; sb[1][w] = sq; sb[2][w] = sa; sb[3][w] = sqa; }
    __syncthreads();
    if (threadIdx.x == 0) {
        float a0=0, a1=0, a2=0, a3=0;
        for (int i = 0; i < 8; i++) { a0+=sb[0][i]; a1+=sb[1][i]; a2+=sb[2][i]; a3+=sb[3][i]; }
        atomicAdd(&g_stats[c][0], (double)a0);
        atomicAdd(&g_stats[c][1], (double)a1);
        atomicAdd(&g_stats[c][2], (double)a2);
        atomicAdd(&g_stats[c][3], (double)a3);
    }
}
__global__ void final_kernel(const float* __restrict__ gamma_a, const float* __restrict__ beta_a,
                             const float* __restrict__ gamma_b, const float* __restrict__ beta_b,
                             float* __restrict__ out)
{
    int c = blockIdx.y;
    int item = blockIdx.x * blockDim.x + threadIdx.x;
    int b = item / HW_, hw = item % HW_;
    const double N = (double)B_ * T_ * HW_;
    double mu_a = g_stats[c][0] / N, va = g_stats[c][1] / N - mu_a*mu_a;
    double mu_b = g_stats[c][2] / N, vb = g_stats[c][3] / N - mu_b*mu_b;
    float sca = gamma_a[c] * (float)(1.0 / sqrt(va + 1e-5));
    float sha = beta_a[c] - (float)mu_a * sca;
    float scb = gamma_b[c] * (float)(1.0 / sqrt(vb + 1e-5));
    float shb = beta_b[c] - (float)mu_b * scb;
    size_t base = (((size_t)b*C_ + c)*T_) * HW_ + hw;
    float prev = 0.f, cur = g_conv[base];
    #pragma unroll
    for (int t = 0; t < T_; t++) {
        float nxt = (t < T_-1) ? g_conv[base + (size_t)(t+1)*HW_] : 0.f;
        float ap = (prev + cur + nxt) * (1.f/3.f);
        out[base + (size_t)t*HW_] = cur*sca + sha + ap*scb + shb;
        prev = cur; cur = nxt;
    }
}

// ---------------------------------------------------------------------------
extern "C" void kernel_launch(void* const* d_in, const int* in_sizes, int n_in,
                              void* d_out, int out_size)
{
    const float* feat    = (const float*)d_in[0];
    const float* Wt      = (const float*)d_in[1];
    const float* bias_p  = (const float*)d_in[2];
    const float* a_w     = (const float*)d_in[3];
    const float* a_b     = (const float*)d_in[4];
    const float* norm_w  = (const float*)d_in[5];
    const float* norm_b  = (const float*)d_in[6];
    const float* normt_w = (const float*)d_in[7];
    const float* normt_b = (const float*)d_in[8];
    const float* qkv_w   = (const float*)d_in[9];
    const float* qkv_b   = (const float*)d_in[10];
    const float* ao_w    = (const float*)d_in[11];
    const float* ao_b    = (const float*)d_in[12];
    const float* b_w     = (const float*)d_in[13];
    const float* bb_w    = (const float*)d_in[14];
    const float* gamma_a = (const float*)d_in[15];
    const float* beta_a  = (const float*)d_in[16];
    const float* gamma_b = (const float*)d_in[17];
    const float* beta_b  = (const float*)d_in[18];
    float* out = (float*)d_out;

    cudaFuncSetAttribute(conv_mma_kernel, cudaFuncAttributeMaxDynamicSharedMemorySize, SMEM_BYTES);

    pool_kernel<<<B_*C_*T_, 128>>>(feat);                               // launch 1
    routing_fused_kernel<<<B_ + 2304, 256>>>(a_w, a_b, norm_w, norm_b,  // launch 2
        normt_w, normt_b, qkv_w, qkv_b, ao_w, ao_b, b_w, bb_w, Wt);
    stage_xs_kernel<<<dim3(8, PR_, NIMG), 256>>>(feat);                 // launch 3
    conv_mma_kernel<<<dim3(28, NIMG), 256, SMEM_BYTES>>>(bias_p);       // launch 4 (profiled)
    stats_kernel<<<dim3(98, 256), 256>>>();                             // launch 5
    final_kernel<<<dim3(98, 256), 256>>>(gamma_a, beta_a, gamma_b, beta_b, out); // launch 6
}

// round 13
// speedup vs baseline: 1.7041x; 1.7041x over previous
#include <cuda_runtime.h>
#include <cuda_fp16.h>
#include <math.h>
#include <stdint.h>

#define B_  8
#define C_  256
#define T_  8
#define H_  56
#define W_  56
#define HW_ (H_*W_)
#define CR_ 64
#define PR_ 58
#define PC_ 64
#define PXI_ (PR_*PC_)     // 3712
#define NIMG 64
#define APH 40             // smem row pitch in halves (80B) — LDSM conflict-free
#define ABUFH (258*APH)
#define BBUFH (128*APH)    // N=128 per block now
#define EPS 132
#define SMEM_BYTES (1024 + 2*ABUFH*2 + 4*BBUFH*2)   // 83264

__device__ float  g_pool[B_*C_*T_];
__device__ float  g_walpha[B_*C_*T_];
__device__ float  g_balpha[B_*C_*T_];
__device__ float  g_conv[(size_t)B_*C_*T_*HW_];
__device__ double g_stats[C_][4];
__device__ float4 g_coef[C_];
__device__ __half g_xs[(size_t)NIMG*PXI_*C_ + 4096]; // padded NHWC fp16 (+OOB guard)
__device__ __half g_wp[9*8*256*32];                  // [tap][kc][o][cc] fp16 (fragment-linear)

// ---------------- helpers ----------------
__device__ __forceinline__ uint32_t smem_to_u32(const void* p) {
    uint32_t a;
    asm("{ .reg .u64 t; cvta.to.shared.u64 t, %1; cvt.u32.u64 %0, t; }" : "=r"(a) : "l"(p));
    return a;
}
__device__ __forceinline__ void cp_async16(uint32_t dst, const void* src) {
    asm volatile("cp.async.ca.shared.global [%0], [%1], 16;" :: "r"(dst), "l"(src));
}
#define CP_COMMIT()   asm volatile("cp.async.commit_group;" ::: "memory")
#define CP_WAIT_ALL() asm volatile("cp.async.wait_all;" ::: "memory")
#define CP_WAIT0()    asm volatile("cp.async.wait_group 0;" ::: "memory")
#define CP_WAIT1()    asm volatile("cp.async.wait_group 1;" ::: "memory")

__device__ __forceinline__ void mma_f16(float* c, const uint32_t* a, uint32_t b0, uint32_t b1) {
    asm volatile("mma.sync.aligned.m16n8k16.row.col.f32.f16.f16.f32 "
        "{%0,%1,%2,%3}, {%4,%5,%6,%7}, {%8,%9}, {%0,%1,%2,%3};"
        : "+f"(c[0]), "+f"(c[1]), "+f"(c[2]), "+f"(c[3])
        : "r"(a[0]), "r"(a[1]), "r"(a[2]), "r"(a[3]), "r"(b0), "r"(b1));
}
__device__ __forceinline__ void ldsm4(uint32_t* r, uint32_t addr) {
    asm volatile("ldmatrix.sync.aligned.m8n8.x4.shared.b16 {%0,%1,%2,%3}, [%4];"
        : "=r"(r[0]), "=r"(r[1]), "=r"(r[2]), "=r"(r[3]) : "r"(addr));
}
__device__ __forceinline__ float qgelu(float x) { return x / (1.f + __expf(-1.702f * x)); }

// ---------------- pool ----------------
__global__ void pool_kernel(const float* __restrict__ feat) {
    int bct = blockIdx.x;
    const float* p = feat + (size_t)bct * HW_;
    float s = 0.f;
    for (int i = threadIdx.x; i < HW_; i += blockDim.x) s += p[i];
    for (int o = 16; o; o >>= 1) s += __shfl_down_sync(0xffffffffu, s, o);
    __shared__ float sb[8];
    int lane = threadIdx.x & 31, w = threadIdx.x >> 5;
    if (lane == 0) sb[w] = s;
    __syncthreads();
    if (threadIdx.x == 0) {
        float t = 0.f;
        for (int i = 0; i < (int)(blockDim.x >> 5); i++) t += sb[i];
        g_pool[bct] = t * (1.f / HW_);
    }
}

// ---------------- routing + weight-prepack + stats-zero (fused grid) ----------------
__global__ void routing_fused_kernel(
    const float* __restrict__ a_w, const float* __restrict__ a_b,
    const float* __restrict__ norm_w, const float* __restrict__ norm_b,
    const float* __restrict__ normt_w, const float* __restrict__ normt_b,
    const float* __restrict__ qkv_w, const float* __restrict__ qkv_b,
    const float* __restrict__ ao_w, const float* __restrict__ ao_b,
    const float* __restrict__ b_w, const float* __restrict__ bb_w,
    const float* __restrict__ Wt)
{
    int tid = threadIdx.x;
    if (blockIdx.x >= B_) {
        int pb = blockIdx.x - B_;
        if (pb == 0) {
            for (int i = tid; i < C_*4; i += 256) ((double*)g_stats)[i] = 0.0;
        }
        int idx = pb * 256 + tid;           // < 589824
        int cc = idx & 31, o = (idx >> 5) & 255, kc = (idx >> 13) & 7, tap = idx >> 16;
        int ky = tap / 3, kx = tap % 3;
        g_wp[idx] = __float2half_rn(Wt[(((size_t)o*C_ + kc*32 + cc)*3 + ky)*3 + kx]);
        return;
    }
    int b = blockIdx.x;
    __shared__ float s_pool[C_][T_], s_x1[CR_][T_], s_x2[CR_][T_], s_xn[CR_][T_];
    __shared__ float s_qkv[3*CR_][T_], s_att[T_][T_], s_o[CR_][T_], s_mu[T_], s_rstd[T_];

    for (int i = tid; i < C_*T_; i += 256) s_pool[i >> 3][i & 7] = g_pool[b*C_*T_ + i];
    __syncthreads();
    for (int idx = tid; idx < CR_*T_; idx += 256) {
        int r = idx >> 3, t = idx & 7;
        float acc = a_b[r];
        const float* wb = a_w + (size_t)r * C_ * 3;
        for (int c = 0; c < C_; c++) {
            float p0 = (t > 0) ? s_pool[c][t-1] : 0.f, p1 = s_pool[c][t], p2 = (t < 7) ? s_pool[c][t+1] : 0.f;
            const float* w = wb + c*3;
            acc += w[0]*p0 + w[1]*p1 + w[2]*p2;
        }
        s_x1[r][t] = acc;
    }
    __syncthreads();
    if (tid < T_) {
        int t = tid;
        float mu = 0.f;
        for (int r = 0; r < CR_; r++) mu += s_x1[r][t];
        mu *= (1.f / CR_);
        float v = 0.f;
        for (int r = 0; r < CR_; r++) { float d = s_x1[r][t] - mu; v += d*d; }
        s_mu[t] = mu; s_rstd[t] = rsqrtf(v * (1.f / CR_) + 1e-6f);
    }
    __syncthreads();
    for (int idx = tid; idx < CR_*T_; idx += 256) {
        int r = idx >> 3, t = idx & 7;
        s_x2[r][t] = qgelu((s_x1[r][t] - s_mu[t]) * s_rstd[t] * norm_w[r] + norm_b[r]);
    }
    __syncthreads();
    if (tid < T_) {
        int t = tid;
        float mu = 0.f;
        for (int r = 0; r < CR_; r++) mu += s_x2[r][t];
        mu *= (1.f / CR_);
        float v = 0.f;
        for (int r = 0; r < CR_; r++) { float d = s_x2[r][t] - mu; v += d*d; }
        s_mu[t] = mu; s_rstd[t] = rsqrtf(v * (1.f / CR_) + 1e-6f);
    }
    __syncthreads();
    for (int idx = tid; idx < CR_*T_; idx += 256) {
        int r = idx >> 3, t = idx & 7;
        s_xn[r][t] = (s_x2[r][t] - s_mu[t]) * s_rstd[t] * normt_w[r] + normt_b[r];
    }
    __syncthreads();
    for (int idx = tid; idx < 3*CR_*T_; idx += 256) {
        int o = idx >> 3, t = idx & 7;
        float acc = qkv_b[o];
        const float* w = qkv_w + (size_t)o * CR_;
        for (int c = 0; c < CR_; c++) acc += w[c] * s_xn[c][t];
        s_qkv[o][t] = acc;
    }
    __syncthreads();
    if (tid < T_*T_) {
        int i = tid >> 3, j = tid & 7;
        float a = 0.f;
        for (int d = 0; d < CR_; d++) a += s_qkv[d][i] * s_qkv[CR_ + d][j];
        s_att[i][j] = a * 0.125f;
    }
    __syncthreads();
    if (tid < T_) {
        int i = tid;
        float m = -1e30f;
        for (int j = 0; j < T_; j++) m = fmaxf(m, s_att[i][j]);
        float sum = 0.f;
        for (int j = 0; j < T_; j++) { float e = __expf(s_att[i][j] - m); s_att[i][j] = e; sum += e; }
        float inv = 1.f / sum;
        for (int j = 0; j < T_; j++) s_att[i][j] *= inv;
    }
    __syncthreads();
    for (int idx = tid; idx < CR_*T_; idx += 256) {
        int d = idx >> 3, t = idx & 7;
        float a = 0.f;
        for (int j = 0; j < T_; j++) a += s_att[t][j] * s_qkv[2*CR_ + d][j];
        s_o[d][t] = a;
    }
    __syncthreads();
    for (int idx = tid; idx < CR_*T_; idx += 256) {
        int r = idx >> 3, t = idx & 7;
        float acc = ao_b[r];
        const float* w = ao_w + (size_t)r * CR_;
        for (int c = 0; c < CR_; c++) acc += w[c] * s_o[c][t];
        s_x1[r][t] = s_x2[r][t] + acc;
    }
    __syncthreads();
    for (int idx = tid; idx < C_*T_; idx += 256) {
        int Co = idx >> 3, t = idx & 7;
        float aw = 0.f, ab = 0.f;
        const float* w1b = b_w  + (size_t)Co * CR_ * 3;
        const float* w2b = bb_w + (size_t)Co * CR_ * 3;
        for (int r = 0; r < CR_; r++) {
            float x0 = (t > 0) ? s_x1[r][t-1] : 0.f, x1 = s_x1[r][t], x2 = (t < 7) ? s_x1[r][t+1] : 0.f;
            const float* w1 = w1b + r*3;
            const float* w2 = w2b + r*3;
            aw += w1[0]*x0 + w1[1]*x1 + w1[2]*x2;
            ab += w2[0]*x0 + w2[1]*x1 + w2[2]*x2;
        }
        g_walpha[b*C_*T_ + idx] = aw;
        g_balpha[b*C_*T_ + idx] = ab;
    }
}

// ---- stage scaled input -> padded NHWC fp16 ----
__global__ void stage_xs_kernel(const float* __restrict__ feat) {
    __shared__ float s[32][65];
    int img = blockIdx.z, r = blockIdx.y, c0 = blockIdx.x * 32;
    int b = img >> 3, t = img & 7;
    int tid = threadIdx.x;
    int x = tid & 63, cl0 = tid >> 6;
    for (int cl = cl0; cl < 32; cl += 4) {
        float v = 0.f;
        if (r >= 1 && r <= 56 && x >= 1 && x <= 56) {
            int c = c0 + cl;
            v = feat[(((size_t)(b*C_ + c))*T_ + t)*HW_ + (r-1)*W_ + (x-1)] * g_walpha[(b*C_ + c)*T_ + t];
        }
        s[cl][x] = v;
    }
    __syncthreads();
    int k = tid & 31, x0 = tid >> 5;
    for (int xx = x0; xx < 64; xx += 8)
        g_xs[((size_t)img*PXI_ + r*PC_ + xx)*C_ + c0 + k] = __float2half_rn(s[k][xx]);
}

// ---------------- conv: implicit GEMM fp16; N=128/block, 2 CTAs/SM ----------------
__global__ void __launch_bounds__(256, 2)
conv_mma_kernel(const float* __restrict__ bias_p)
{
    extern __shared__ char smc[];
    float*  bias_sm = (float*)smc;            // 128 floats
    __half* As = (__half*)(smc + 1024);       // 2 x ABUFH halves
    __half* Bs = As + 2*ABUFH;                // 4 x BBUFH halves (ring)
    uint32_t as_u = smem_to_u32(As);
    uint32_t bs_u = smem_to_u32(Bs);

    int tid = threadIdx.x, lane = tid & 31, wid = tid >> 5;
    int wm = wid >> 2, wn = wid & 3;          // warps 2(M) x 4(N=32 each)
    int mg = lane >> 2, tg = lane & 3;
    int img = blockIdx.z, bn = blockIdx.y, yt = blockIdx.x;
    int b = img >> 3, t = img & 7;
    size_t imgP = (size_t)img * PXI_ + (size_t)yt * 128;

    // per-lane ldmatrix address offsets (bytes)
    uint32_t aoff_l = (uint32_t)((((lane & 7) + (lane & 8)) * APH + ((lane & 16) >> 1)) * 2);
    uint32_t boff_l = (uint32_t)((((lane & 7) + ((lane & 16) >> 1)) * APH + (lane & 8)) * 2);

    if (tid < 128) bias_sm[tid] = g_balpha[(b*C_ + bn*128 + tid)*T_ + t] * bias_p[bn*128 + tid];

    // preload A(kc=0) -> Abuf0, B tiles tt=0,1 -> ring bufs 0,1
    const __half* srcA0 = g_xs + imgP*C_;
    for (int idx = tid; idx < 258*4; idx += 256) {
        int p = idx >> 2, q = idx & 3;
        cp_async16(as_u + (uint32_t)(p*80 + q*16), srcA0 + (size_t)p*C_ + q*8);
    }
    for (int idx = tid; idx < 1024; idx += 256) {
        int t0 = idx >> 9, r = idx & 511;
        cp_async16(bs_u + (uint32_t)(t0*(BBUFH*2)) + (uint32_t)((r>>2)*80 + (r&3)*16),
                   g_wp + ((size_t)((t0 % 9)*8 + t0/9)*256 + bn*128)*32 + r*8);
    }
    CP_COMMIT(); CP_WAIT_ALL();
    __syncthreads();

    float acc[4][4][4] = {};

    for (int tt = 0; tt < 72; tt++) {
        int kc = tt / 9, tap = tt % 9;
        bool committed = false;
        // single prefetch group per tap: B(tt+2) + A(kc+1) slice
        if (tt + 2 < 72) {
            int n = tt + 2;
            const __half* wp = g_wp + ((size_t)((n % 9)*8 + n/9)*256 + bn*128)*32;
            uint32_t dstb = bs_u + (uint32_t)(n & 3)*(BBUFH*2);
            for (int idx = tid; idx < 512; idx += 256) {
                cp_async16(dstb + (uint32_t)((idx>>2)*80 + (idx&3)*16), wp + idx*8);
            }
            committed = true;
        }
        if (kc < 7 && tap < 7) {
            const __half* srcAn = g_xs + imgP*C_ + (size_t)(kc+1)*32;
            uint32_t dsta = as_u + (uint32_t)(((kc+1) & 1)*(ABUFH*2));
            int r0 = tap*37, r1 = min(r0 + 37, 258);
            for (int idx = tid + r0*4; idx < r1*4; idx += 256) {
                int p = idx >> 2, q = idx & 3;
                cp_async16(dsta + (uint32_t)(p*80 + q*16), srcAn + (size_t)p*C_ + q*8);
            }
            committed = true;
        }
        if (committed) CP_COMMIT();

        int off = (tap/3)*64 + (tap%3);
        uint32_t abase = as_u + (uint32_t)((kc & 1)*(ABUFH*2)) + (uint32_t)((off + wm*64)*80) + aoff_l;
        uint32_t bbase = bs_u + (uint32_t)((tt & 3)*(BBUFH*2)) + (uint32_t)((wn*32)*80) + boff_l;
        #pragma unroll
        for (int ks = 0; ks < 2; ks++) {
            uint32_t af[4][4];
            #pragma unroll
            for (int i = 0; i < 4; i++)
                ldsm4(af[i], abase + (uint32_t)(i*16*80 + ks*32));
            #pragma unroll
            for (int jp = 0; jp < 2; jp++) {
                uint32_t bf[4];
                ldsm4(bf, bbase + (uint32_t)(jp*16*80 + ks*32));
                #pragma unroll
                for (int i = 0; i < 4; i++) {
                    mma_f16(acc[i][2*jp],   af[i], bf[0], bf[1]);
                    mma_f16(acc[i][2*jp+1], af[i], bf[2], bf[3]);
                }
            }
        }
        if (committed) CP_WAIT1();
        else          CP_WAIT0();
        __syncthreads();
    }

    // epilogue: transpose through smem (64 ch at a time), coalesced float4 stores
    float* ep = (float*)(smc + 1024);   // 64 x EPS floats = 33.8KB (fits in A region)
    #pragma unroll
    for (int h = 0; h < 2; h++) {
        if ((wn >> 1) == h) {
            #pragma unroll
            for (int i = 0; i < 4; i++)
                #pragma unroll
                for (int j = 0; j < 4; j++)
                    #pragma unroll
                    for (int e = 0; e < 4; e++) {
                        int nl = (wn & 1)*32 + j*8 + tg*2 + (e & 1);   // 0..63
                        int m  = wm*64 + i*16 + mg + ((e >> 1)*8);     // 0..127
                        ep[nl*EPS + m] = acc[i][j][e] + bias_sm[h*64 + nl];
                    }
        }
        __syncthreads();
        int sub = lane >> 4, xi = lane & 15;
        #pragma unroll
        for (int it = 0; it < 8; it++) {
            int rowIdx = it*16 + wid*2 + sub;   // 0..127 = ch(64) x ry(2)
            int ch = rowIdx >> 1, ry = rowIdx & 1;
            if (xi < 14) {
                float4 v = *(const float4*)&ep[ch*EPS + ry*64 + xi*4];
                int o = bn*128 + h*64 + ch;
                *(float4*)&g_conv[(((size_t)(b*C_ + o))*T_ + t)*HW_ + (yt*2 + ry)*W_ + xi*4] = v;
            }
        }
        __syncthreads();
    }
}

// ---------------- stats + coef + final ----------------
__global__ void stats_kernel() {
    int c = blockIdx.y;
    int item = blockIdx.x * blockDim.x + threadIdx.x;
    int b = item / HW_, hw = item % HW_;
    size_t base = (((size_t)b*C_ + c)*T_) * HW_ + hw;
    float so = 0.f, sq = 0.f, sa = 0.f, sqa = 0.f, prev = 0.f, cur = g_conv[base];
    #pragma unroll
    for (int t = 0; t < T_; t++) {
        float nxt = (t < T_-1) ? g_conv[base + (size_t)(t+1)*HW_] : 0.f;
        so += cur; sq += cur*cur;
        float ap = (prev + cur + nxt) * (1.f/3.f);
        sa += ap; sqa += ap*ap;
        prev = cur; cur = nxt;
    }
    __shared__ float sb[4][8];
    for (int o = 16; o; o >>= 1) {
        so += __shfl_down_sync(0xffffffffu, so, o);
        sq += __shfl_down_sync(0xffffffffu, sq, o);
        sa += __shfl_down_sync(0xffffffffu, sa, o);
        sqa += __shfl_down_sync(0xffffffffu, sqa, o);
    }
    int lane = threadIdx.x & 31, w = threadIdx.x >> 5;
    if (lane == 0) { sb[0][w] = so; sb[1][w] = sq; sb[2][w] = sa; sb[3][w] = sqa; }
    __syncthreads();
    if (threadIdx.x == 0) {
        float a0=0, a1=0, a2=0, a3=0;
        for (int i = 0; i < 8; i++) { a0+=sb[0][i]; a1+=sb[1][i]; a2+=sb[2][i]; a3+=sb[3][i]; }
        atomicAdd(&g_stats[c][0], (double)a0);
        atomicAdd(&g_stats[c][1], (double)a1);
        atomicAdd(&g_stats[c][2], (double)a2);
        atomicAdd(&g_stats[c][3], (double)a3);
    }
}
__global__ void coef_kernel(const float* __restrict__ gamma_a, const float* __restrict__ beta_a,
                            const float* __restrict__ gamma_b, const float* __restrict__ beta_b)
{
    int c = threadIdx.x;
    const double N = (double)B_ * T_ * HW_;
    double mu_a = g_stats[c][0] / N, va = g_stats[c][1] / N - mu_a*mu_a;
    double mu_b = g_stats[c][2] / N, vb = g_stats[c][3] / N - mu_b*mu_b;
    float sca = gamma_a[c] * (float)(1.0 / sqrt(va + 1e-5));
    float sha = beta_a[c] - (float)mu_a * sca;
    float scb = gamma_b[c] * (float)(1.0 / sqrt(vb + 1e-5));
    float shb = beta_b[c] - (float)mu_b * scb;
    g_coef[c] = make_float4(sca, sha, scb, shb);
}
__global__ void final_kernel(float* __restrict__ out)
{
    int c = blockIdx.y;
    int item = blockIdx.x * blockDim.x + threadIdx.x;
    int b = item / HW_, hw = item % HW_;
    float4 cf = g_coef[c];
    size_t base = (((size_t)b*C_ + c)*T_) * HW_ + hw;
    float prev = 0.f, cur = g_conv[base];
    #pragma unroll
    for (int t = 0; t < T_; t++) {
        float nxt = (t < T_-1) ? g_conv[base + (size_t)(t+1)*HW_] : 0.f;
        float ap = (prev + cur + nxt) * (1.f/3.f);
        out[base + (size_t)t*HW_] = cur*cf.x + cf.y + ap*cf.z + cf.w;
        prev = cur; cur = nxt;
    }
}

// ---------------------------------------------------------------------------
extern "C" void kernel_launch(void* const* d_in, const int* in_sizes, int n_in,
                              void* d_out, int out_size)
{
    const float* feat    = (const float*)d_in[0];
    const float* Wt      = (const float*)d_in[1];
    const float* bias_p  = (const float*)d_in[2];
    const float* a_w     = (const float*)d_in[3];
    const float* a_b     = (const float*)d_in[4];
    const float* norm_w  = (const float*)d_in[5];
    const float* norm_b  = (const float*)d_in[6];
    const float* normt_w = (const float*)d_in[7];
    const float* normt_b = (const float*)d_in[8];
    const float* qkv_w   = (const float*)d_in[9];
    const float* qkv_b   = (const float*)d_in[10];
    const float* ao_w    = (const float*)d_in[11];
    const float* ao_b    = (const float*)d_in[12];
    const float* b_w     = (const float*)d_in[13];
    const float* bb_w    = (const float*)d_in[14];
    const float* gamma_a = (const float*)d_in[15];
    const float* beta_a  = (const float*)d_in[16];
    const float* gamma_b = (const float*)d_in[17];
    const float* beta_b  = (const float*)d_in[18];
    float* out = (float*)d_out;

    cudaFuncSetAttribute(conv_mma_kernel, cudaFuncAttributeMaxDynamicSharedMemorySize, SMEM_BYTES);

    pool_kernel<<<B_*C_*T_, 128>>>(feat);                               // launch 1
    routing_fused_kernel<<<B_ + 2304, 256>>>(a_w, a_b, norm_w, norm_b,  // launch 2
        normt_w, normt_b, qkv_w, qkv_b, ao_w, ao_b, b_w, bb_w, Wt);
    stage_xs_kernel<<<dim3(8, PR_, NIMG), 256>>>(feat);                 // launch 3
    conv_mma_kernel<<<dim3(28, 2, NIMG), 256, SMEM_BYTES>>>(bias_p);    // launch 4 (profiled)
    stats_kernel<<<dim3(98, 256), 256>>>();                             // launch 5
    coef_kernel<<<1, 256>>>(gamma_a, beta_a, gamma_b, beta_b);          // launch 6
    final_kernel<<<dim3(98, 256), 256>>>(out);                          // launch 7
}

// round 14
// speedup vs baseline: 1.8244x; 1.0706x over previous
#include <cuda_runtime.h>
#include <cuda_fp16.h>
#include <math.h>
#include <stdint.h>

#define B_  8
#define C_  256
#define T_  8
#define H_  56
#define W_  56
#define HW_ (H_*W_)
#define CR_ 64
#define PR_ 58
#define PC_ 64
#define PXI_ (PR_*PC_)     // 3712
#define NIMG 64
#define APH 40             // smem row pitch in halves (80B) — LDSM conflict-free
#define ABUFH (258*APH)
#define BBUFH (128*APH)    // N=128 per block
#define EPS 132
#define SMEM_BYTES (1024 + 2*ABUFH*2 + 4*BBUFH*2)   // 83264

__device__ float  g_pool[B_*C_*T_];
__device__ float  g_walpha[B_*C_*T_];
__device__ float  g_balpha[B_*C_*T_];
__device__ float  g_conv[(size_t)B_*C_*T_*HW_];
__device__ double g_stats[C_][4];
__device__ float4 g_coef[C_];
__device__ __half g_xs[(size_t)NIMG*PXI_*C_ + 4096]; // padded NHWC fp16 (+OOB guard)
__device__ __half g_wp[9*8*256*32];                  // [tap][kc][o][cc] fp16 (fragment-linear)

// ---------------- helpers ----------------
__device__ __forceinline__ uint32_t smem_to_u32(const void* p) {
    uint32_t a;
    asm("{ .reg .u64 t; cvta.to.shared.u64 t, %1; cvt.u32.u64 %0, t; }" : "=r"(a) : "l"(p));
    return a;
}
__device__ __forceinline__ void cp_async16(uint32_t dst, const void* src) {
    asm volatile("cp.async.ca.shared.global [%0], [%1], 16;" :: "r"(dst), "l"(src));
}
#define CP_COMMIT()   asm volatile("cp.async.commit_group;" ::: "memory")
#define CP_WAIT_ALL() asm volatile("cp.async.wait_all;" ::: "memory")
#define CP_WAIT0()    asm volatile("cp.async.wait_group 0;" ::: "memory")
#define CP_WAIT1()    asm volatile("cp.async.wait_group 1;" ::: "memory")

__device__ __forceinline__ void mma_f16(float* c, const uint32_t* a, uint32_t b0, uint32_t b1) {
    asm volatile("mma.sync.aligned.m16n8k16.row.col.f32.f16.f16.f32 "
        "{%0,%1,%2,%3}, {%4,%5,%6,%7}, {%8,%9}, {%0,%1,%2,%3};"
        : "+f"(c[0]), "+f"(c[1]), "+f"(c[2]), "+f"(c[3])
        : "r"(a[0]), "r"(a[1]), "r"(a[2]), "r"(a[3]), "r"(b0), "r"(b1));
}
__device__ __forceinline__ void ldsm4(uint32_t* r, uint32_t addr) {
    asm volatile("ldmatrix.sync.aligned.m8n8.x4.shared.b16 {%0,%1,%2,%3}, [%4];"
        : "=r"(r[0]), "=r"(r[1]), "=r"(r[2]), "=r"(r[3]) : "r"(addr));
}
__device__ __forceinline__ float qgelu(float x) { return x / (1.f + __expf(-1.702f * x)); }

// ---------------- pool ----------------
__global__ void pool_kernel(const float* __restrict__ feat) {
    int bct = blockIdx.x;
    const float* p = feat + (size_t)bct * HW_;
    float s = 0.f;
    for (int i = threadIdx.x; i < HW_; i += blockDim.x) s += p[i];
    for (int o = 16; o; o >>= 1) s += __shfl_down_sync(0xffffffffu, s, o);
    __shared__ float sb[8];
    int lane = threadIdx.x & 31, w = threadIdx.x >> 5;
    if (lane == 0) sb[w] = s;
    __syncthreads();
    if (threadIdx.x == 0) {
        float t = 0.f;
        for (int i = 0; i < (int)(blockDim.x >> 5); i++) t += sb[i];
        g_pool[bct] = t * (1.f / HW_);
    }
}

// ---------------- routing + weight-prepack + stats-zero (fused grid) ----------------
__global__ void routing_fused_kernel(
    const float* __restrict__ a_w, const float* __restrict__ a_b,
    const float* __restrict__ norm_w, const float* __restrict__ norm_b,
    const float* __restrict__ normt_w, const float* __restrict__ normt_b,
    const float* __restrict__ qkv_w, const float* __restrict__ qkv_b,
    const float* __restrict__ ao_w, const float* __restrict__ ao_b,
    const float* __restrict__ b_w, const float* __restrict__ bb_w,
    const float* __restrict__ Wt)
{
    int tid = threadIdx.x;
    if (blockIdx.x >= B_) {
        int pb = blockIdx.x - B_;
        if (pb == 0) {
            for (int i = tid; i < C_*4; i += 256) ((double*)g_stats)[i] = 0.0;
        }
        int idx = pb * 256 + tid;           // < 589824
        int cc = idx & 31, o = (idx >> 5) & 255, kc = (idx >> 13) & 7, tap = idx >> 16;
        int ky = tap / 3, kx = tap % 3;
        g_wp[idx] = __float2half_rn(Wt[(((size_t)o*C_ + kc*32 + cc)*3 + ky)*3 + kx]);
        return;
    }
    int b = blockIdx.x;
    __shared__ float s_pool[C_][T_], s_x1[CR_][T_], s_x2[CR_][T_], s_xn[CR_][T_];
    __shared__ float s_qkv[3*CR_][T_], s_att[T_][T_], s_o[CR_][T_], s_mu[T_], s_rstd[T_];

    for (int i = tid; i < C_*T_; i += 256) s_pool[i >> 3][i & 7] = g_pool[b*C_*T_ + i];
    __syncthreads();
    for (int idx = tid; idx < CR_*T_; idx += 256) {
        int r = idx >> 3, t = idx & 7;
        float acc = a_b[r];
        const float* wb = a_w + (size_t)r * C_ * 3;
        for (int c = 0; c < C_; c++) {
            float p0 = (t > 0) ? s_pool[c][t-1] : 0.f, p1 = s_pool[c][t], p2 = (t < 7) ? s_pool[c][t+1] : 0.f;
            const float* w = wb + c*3;
            acc += w[0]*p0 + w[1]*p1 + w[2]*p2;
        }
        s_x1[r][t] = acc;
    }
    __syncthreads();
    if (tid < T_) {
        int t = tid;
        float mu = 0.f;
        for (int r = 0; r < CR_; r++) mu += s_x1[r][t];
        mu *= (1.f / CR_);
        float v = 0.f;
        for (int r = 0; r < CR_; r++) { float d = s_x1[r][t] - mu; v += d*d; }
        s_mu[t] = mu; s_rstd[t] = rsqrtf(v * (1.f / CR_) + 1e-6f);
    }
    __syncthreads();
    for (int idx = tid; idx < CR_*T_; idx += 256) {
        int r = idx >> 3, t = idx & 7;
        s_x2[r][t] = qgelu((s_x1[r][t] - s_mu[t]) * s_rstd[t] * norm_w[r] + norm_b[r]);
    }
    __syncthreads();
    if (tid < T_) {
        int t = tid;
        float mu = 0.f;
        for (int r = 0; r < CR_; r++) mu += s_x2[r][t];
        mu *= (1.f / CR_);
        float v = 0.f;
        for (int r = 0; r < CR_; r++) { float d = s_x2[r][t] - mu; v += d*d; }
        s_mu[t] = mu; s_rstd[t] = rsqrtf(v * (1.f / CR_) + 1e-6f);
    }
    __syncthreads();
    for (int idx = tid; idx < CR_*T_; idx += 256) {
        int r = idx >> 3, t = idx & 7;
        s_xn[r][t] = (s_x2[r][t] - s_mu[t]) * s_rstd[t] * normt_w[r] + normt_b[r];
    }
    __syncthreads();
    for (int idx = tid; idx < 3*CR_*T_; idx += 256) {
        int o = idx >> 3, t = idx & 7;
        float acc = qkv_b[o];
        const float* w = qkv_w + (size_t)o * CR_;
        for (int c = 0; c < CR_; c++) acc += w[c] * s_xn[c][t];
        s_qkv[o][t] = acc;
    }
    __syncthreads();
    if (tid < T_*T_) {
        int i = tid >> 3, j = tid & 7;
        float a = 0.f;
        for (int d = 0; d < CR_; d++) a += s_qkv[d][i] * s_qkv[CR_ + d][j];
        s_att[i][j] = a * 0.125f;
    }
    __syncthreads();
    if (tid < T_) {
        int i = tid;
        float m = -1e30f;
        for (int j = 0; j < T_; j++) m = fmaxf(m, s_att[i][j]);
        float sum = 0.f;
        for (int j = 0; j < T_; j++) { float e = __expf(s_att[i][j] - m); s_att[i][j] = e; sum += e; }
        float inv = 1.f / sum;
        for (int j = 0; j < T_; j++) s_att[i][j] *= inv;
    }
    __syncthreads();
    for (int idx = tid; idx < CR_*T_; idx += 256) {
        int d = idx >> 3, t = idx & 7;
        float a = 0.f;
        for (int j = 0; j < T_; j++) a += s_att[t][j] * s_qkv[2*CR_ + d][j];
        s_o[d][t] = a;
    }
    __syncthreads();
    for (int idx = tid; idx < CR_*T_; idx += 256) {
        int r = idx >> 3, t = idx & 7;
        float acc = ao_b[r];
        const float* w = ao_w + (size_t)r * CR_;
        for (int c = 0; c < CR_; c++) acc += w[c] * s_o[c][t];
        s_x1[r][t] = s_x2[r][t] + acc;
    }
    __syncthreads();
    for (int idx = tid; idx < C_*T_; idx += 256) {
        int Co = idx >> 3, t = idx & 7;
        float aw = 0.f, ab = 0.f;
        const float* w1b = b_w  + (size_t)Co * CR_ * 3;
        const float* w2b = bb_w + (size_t)Co * CR_ * 3;
        for (int r = 0; r < CR_; r++) {
            float x0 = (t > 0) ? s_x1[r][t-1] : 0.f, x1 = s_x1[r][t], x2 = (t < 7) ? s_x1[r][t+1] : 0.f;
            const float* w1 = w1b + r*3;
            const float* w2 = w2b + r*3;
            aw += w1[0]*x0 + w1[1]*x1 + w1[2]*x2;
            ab += w2[0]*x0 + w2[1]*x1 + w2[2]*x2;
        }
        g_walpha[b*C_*T_ + idx] = aw;
        g_balpha[b*C_*T_ + idx] = ab;
    }
}

// ---- stage scaled input -> padded NHWC fp16 ----
__global__ void stage_xs_kernel(const float* __restrict__ feat) {
    __shared__ float s[32][65];
    int img = blockIdx.z, r = blockIdx.y, c0 = blockIdx.x * 32;
    int b = img >> 3, t = img & 7;
    int tid = threadIdx.x;
    int x = tid & 63, cl0 = tid >> 6;
    for (int cl = cl0; cl < 32; cl += 4) {
        float v = 0.f;
        if (r >= 1 && r <= 56 && x >= 1 && x <= 56) {
            int c = c0 + cl;
            v = feat[(((size_t)(b*C_ + c))*T_ + t)*HW_ + (r-1)*W_ + (x-1)] * g_walpha[(b*C_ + c)*T_ + t];
        }
        s[cl][x] = v;
    }
    __syncthreads();
    int k = tid & 31, x0 = tid >> 5;
    for (int xx = x0; xx < 64; xx += 8)
        g_xs[((size_t)img*PXI_ + r*PC_ + xx)*C_ + c0 + k] = __float2half_rn(s[k][xx]);
}

// ---------------- conv: implicit GEMM fp16; 4 warps (2Mx2N, 64x64 tiles), 2 CTAs/SM ----------------
__global__ void __launch_bounds__(128, 2)
conv_mma_kernel(const float* __restrict__ bias_p)
{
    extern __shared__ char smc[];
    float*  bias_sm = (float*)smc;            // 128 floats
    __half* As = (__half*)(smc + 1024);       // 2 x ABUFH halves
    __half* Bs = As + 2*ABUFH;                // 4 x BBUFH halves (ring)
    uint32_t as_u = smem_to_u32(As);
    uint32_t bs_u = smem_to_u32(Bs);

    int tid = threadIdx.x, lane = tid & 31, wid = tid >> 5;
    int wm = wid >> 1, wn = wid & 1;          // warps 2(M=64) x 2(N=64)
    int mg = lane >> 2, tg = lane & 3;
    int img = blockIdx.z, bn = blockIdx.y, yt = blockIdx.x;
    int b = img >> 3, t = img & 7;
    size_t imgP = (size_t)img * PXI_ + (size_t)yt * 128;

    // per-lane ldmatrix address offsets (bytes)
    uint32_t aoff_l = (uint32_t)((((lane & 7) + (lane & 8)) * APH + ((lane & 16) >> 1)) * 2);
    uint32_t boff_l = (uint32_t)((((lane & 7) + ((lane & 16) >> 1)) * APH + (lane & 8)) * 2);

    bias_sm[tid] = g_balpha[(b*C_ + bn*128 + tid)*T_ + t] * bias_p[bn*128 + tid];

    // preload A(kc=0) -> Abuf0, B tiles tt=0,1 -> ring bufs 0,1
    const __half* srcA0 = g_xs + imgP*C_;
    for (int idx = tid; idx < 258*4; idx += 128) {
        int p = idx >> 2, q = idx & 3;
        cp_async16(as_u + (uint32_t)(p*80 + q*16), srcA0 + (size_t)p*C_ + q*8);
    }
    for (int idx = tid; idx < 1024; idx += 128) {
        int t0 = idx >> 9, r = idx & 511;
        cp_async16(bs_u + (uint32_t)(t0*(BBUFH*2)) + (uint32_t)((r>>2)*80 + (r&3)*16),
                   g_wp + ((size_t)((t0 % 9)*8 + t0/9)*256 + bn*128)*32 + r*8);
    }
    CP_COMMIT(); CP_WAIT_ALL();
    __syncthreads();

    float acc[4][8][4] = {};

    for (int tt = 0; tt < 72; tt++) {
        int kc = tt / 9, tap = tt % 9;
        bool committed = false;
        // single prefetch group per tap: B(tt+2) + A(kc+1) slice
        if (tt + 2 < 72) {
            int n = tt + 2;
            const __half* wp = g_wp + ((size_t)((n % 9)*8 + n/9)*256 + bn*128)*32;
            uint32_t dstb = bs_u + (uint32_t)(n & 3)*(BBUFH*2);
            for (int idx = tid; idx < 512; idx += 128) {
                cp_async16(dstb + (uint32_t)((idx>>2)*80 + (idx&3)*16), wp + idx*8);
            }
            committed = true;
        }
        if (kc < 7 && tap < 7) {
            const __half* srcAn = g_xs + imgP*C_ + (size_t)(kc+1)*32;
            uint32_t dsta = as_u + (uint32_t)(((kc+1) & 1)*(ABUFH*2));
            int r0 = tap*37, r1 = min(r0 + 37, 258);
            for (int idx = tid + r0*4; idx < r1*4; idx += 128) {
                int p = idx >> 2, q = idx & 3;
                cp_async16(dsta + (uint32_t)(p*80 + q*16), srcAn + (size_t)p*C_ + q*8);
            }
            committed = true;
        }
        if (committed) CP_COMMIT();

        int off = (tap/3)*64 + (tap%3);
        uint32_t abase = as_u + (uint32_t)((kc & 1)*(ABUFH*2)) + (uint32_t)((off + wm*64)*80) + aoff_l;
        uint32_t bbase = bs_u + (uint32_t)((tt & 3)*(BBUFH*2)) + (uint32_t)((wn*64)*80) + boff_l;
        #pragma unroll
        for (int ks = 0; ks < 2; ks++) {
            uint32_t af[4][4];
            #pragma unroll
            for (int i = 0; i < 4; i++)
                ldsm4(af[i], abase + (uint32_t)(i*16*80 + ks*32));
            #pragma unroll
            for (int jp = 0; jp < 4; jp++) {
                uint32_t bf[4];
                ldsm4(bf, bbase + (uint32_t)(jp*16*80 + ks*32));
                #pragma unroll
                for (int i = 0; i < 4; i++) {
                    mma_f16(acc[i][2*jp],   af[i], bf[0], bf[1]);
                    mma_f16(acc[i][2*jp+1], af[i], bf[2], bf[3]);
                }
            }
        }
        if (committed) CP_WAIT1();
        else          CP_WAIT0();
        __syncthreads();
    }

    // epilogue: transpose through smem (64 ch at a time), coalesced float4 stores
    float* ep = (float*)(smc + 1024);   // 64 x EPS floats = 33.8KB (fits in A region)
    #pragma unroll
    for (int h = 0; h < 2; h++) {
        if (wn == h) {
            #pragma unroll
            for (int i = 0; i < 4; i++)
                #pragma unroll
                for (int j = 0; j < 8; j++)
                    #pragma unroll
                    for (int e = 0; e < 4; e++) {
                        int nl = j*8 + tg*2 + (e & 1);                 // 0..63
                        int m  = wm*64 + i*16 + mg + ((e >> 1)*8);     // 0..127
                        ep[nl*EPS + m] = acc[i][j][e] + bias_sm[h*64 + nl];
                    }
        }
        __syncthreads();
        int sub = lane >> 4, xi = lane & 15;
        #pragma unroll
        for (int it = 0; it < 16; it++) {
            int rowIdx = it*8 + wid*2 + sub;   // 0..127 = ch(64) x ry(2)
            int ch = rowIdx >> 1, ry = rowIdx & 1;
            if (xi < 14) {
                float4 v = *(const float4*)&ep[ch*EPS + ry*64 + xi*4];
                int o = bn*128 + h*64 + ch;
                *(float4*)&g_conv[(((size_t)(b*C_ + o))*T_ + t)*HW_ + (yt*2 + ry)*W_ + xi*4] = v;
            }
        }
        __syncthreads();
    }
}

// ---------------- stats + coef + final ----------------
__global__ void stats_kernel() {
    int c = blockIdx.y;
    int item = blockIdx.x * blockDim.x + threadIdx.x;
    int b = item / HW_, hw = item % HW_;
    size_t base = (((size_t)b*C_ + c)*T_) * HW_ + hw;
    float so = 0.f, sq = 0.f, sa = 0.f, sqa = 0.f, prev = 0.f, cur = g_conv[base];
    #pragma unroll
    for (int t = 0; t < T_; t++) {
        float nxt = (t < T_-1) ? g_conv[base + (size_t)(t+1)*HW_] : 0.f;
        so += cur; sq += cur*cur;
        float ap = (prev + cur + nxt) * (1.f/3.f);
        sa += ap; sqa += ap*ap;
        prev = cur; cur = nxt;
    }
    __shared__ float sb[4][8];
    for (int o = 16; o; o >>= 1) {
        so += __shfl_down_sync(0xffffffffu, so, o);
        sq += __shfl_down_sync(0xffffffffu, sq, o);
        sa += __shfl_down_sync(0xffffffffu, sa, o);
        sqa += __shfl_down_sync(0xffffffffu, sqa, o);
    }
    int lane = threadIdx.x & 31, w = threadIdx.x >> 5;
    if (lane == 0) { sb[0][w] = so; sb[1][w] = sq; sb[2][w] = sa; sb[3][w] = sqa; }
    __syncthreads();
    if (threadIdx.x == 0) {
        float a0=0, a1=0, a2=0, a3=0;
        for (int i = 0; i < 8; i++) { a0+=sb[0][i]; a1+=sb[1][i]; a2+=sb[2][i]; a3+=sb[3][i]; }
        atomicAdd(&g_stats[c][0], (double)a0);
        atomicAdd(&g_stats[c][1], (double)a1);
        atomicAdd(&g_stats[c][2], (double)a2);
        atomicAdd(&g_stats[c][3], (double)a3);
    }
}
__global__ void coef_kernel(const float* __restrict__ gamma_a, const float* __restrict__ beta_a,
                            const float* __restrict__ gamma_b, const float* __restrict__ beta_b)
{
    int c = threadIdx.x;
    const double N = (double)B_ * T_ * HW_;
    double mu_a = g_stats[c][0] / N, va = g_stats[c][1] / N - mu_a*mu_a;
    double mu_b = g_stats[c][2] / N, vb = g_stats[c][3] / N - mu_b*mu_b;
    float sca = gamma_a[c] * (float)(1.0 / sqrt(va + 1e-5));
    float sha = beta_a[c] - (float)mu_a * sca;
    float scb = gamma_b[c] * (float)(1.0 / sqrt(vb + 1e-5));
    float shb = beta_b[c] - (float)mu_b * scb;
    g_coef[c] = make_float4(sca, sha, scb, shb);
}
__global__ void final_kernel(float* __restrict__ out)
{
    int c = blockIdx.y;
    int item = blockIdx.x * blockDim.x + threadIdx.x;
    int b = item / HW_, hw = item % HW_;
    float4 cf = g_coef[c];
    size_t base = (((size_t)b*C_ + c)*T_) * HW_ + hw;
    float prev = 0.f, cur = g_conv[base];
    #pragma unroll
    for (int t = 0; t < T_; t++) {
        float nxt = (t < T_-1) ? g_conv[base + (size_t)(t+1)*HW_] : 0.f;
        float ap = (prev + cur + nxt) * (1.f/3.f);
        out[base + (size_t)t*HW_] = cur*cf.x + cf.y + ap*cf.z + cf.w;
        prev = cur; cur = nxt;
    }
}

// ---------------------------------------------------------------------------
extern "C" void kernel_launch(void* const* d_in, const int* in_sizes, int n_in,
                              void* d_out, int out_size)
{
    const float* feat    = (const float*)d_in[0];
    const float* Wt      = (const float*)d_in[1];
    const float* bias_p  = (const float*)d_in[2];
    const float* a_w     = (const float*)d_in[3];
    const float* a_b     = (const float*)d_in[4];
    const float* norm_w  = (const float*)d_in[5];
    const float* norm_b  = (const float*)d_in[6];
    const float* normt_w = (const float*)d_in[7];
    const float* normt_b = (const float*)d_in[8];
    const float* qkv_w   = (const float*)d_in[9];
    const float* qkv_b   = (const float*)d_in[10];
    const float* ao_w    = (const float*)d_in[11];
    const float* ao_b    = (const float*)d_in[12];
    const float* b_w     = (const float*)d_in[13];
    const float* bb_w    = (const float*)d_in[14];
    const float* gamma_a = (const float*)d_in[15];
    const float* beta_a  = (const float*)d_in[16];
    const float* gamma_b = (const float*)d_in[17];
    const float* beta_b  = (const float*)d_in[18];
    float* out = (float*)d_out;

    cudaFuncSetAttribute(conv_mma_kernel, cudaFuncAttributeMaxDynamicSharedMemorySize, SMEM_BYTES);

    pool_kernel<<<B_*C_*T_, 128>>>(feat);                               // launch 1
    routing_fused_kernel<<<B_ + 2304, 256>>>(a_w, a_b, norm_w, norm_b,  // launch 2
        normt_w, normt_b, qkv_w, qkv_b, ao_w, ao_b, b_w, bb_w, Wt);
    stage_xs_kernel<<<dim3(8, PR_, NIMG), 256>>>(feat);                 // launch 3
    conv_mma_kernel<<<dim3(28, 2, NIMG), 128, SMEM_BYTES>>>(bias_p);    // launch 4 (profiled)
    stats_kernel<<<dim3(98, 256), 256>>>();                             // launch 5
    coef_kernel<<<1, 256>>>(gamma_a, beta_a, gamma_b, beta_b);          // launch 6
    final_kernel<<<dim3(98, 256), 256>>>(out);                          // launch 7
}

// round 15
// speedup vs baseline: 1.8812x; 1.0311x over previous
#include <cuda_runtime.h>
#include <cuda_fp16.h>
#include <math.h>
#include <stdint.h>

#define B_  8
#define C_  256
#define T_  8
#define H_  56
#define W_  56
#define HW_ (H_*W_)
#define CR_ 64
#define PR_ 58
#define PC_ 64
#define PXI_ (PR_*PC_)     // 3712
#define NIMG 64
#define APH 72             // smem row pitch in halves (144B) — LDSM conflict-free
#define ABUFH (258*APH)
#define BBUFH (128*APH)
#define EPS 132
#define SMEM_BYTES (1024 + 2*ABUFH*2 + 2*BBUFH*2)   // 112192

__device__ float  g_pool[B_*C_*T_];
__device__ float  g_walpha[B_*C_*T_];
__device__ float  g_balpha[B_*C_*T_];
__device__ float  g_conv[(size_t)B_*C_*T_*HW_];
__device__ double g_stats[C_][4];
__device__ float4 g_coef[C_];
__device__ __half g_xs[(size_t)NIMG*PXI_*C_ + 4096]; // padded NHWC fp16 (+OOB guard)
__device__ __half g_wp[9*8*256*32];                  // [tap][kc32][o][cc] fp16

// ---------------- helpers ----------------
__device__ __forceinline__ uint32_t smem_to_u32(const void* p) {
    uint32_t a;
    asm("{ .reg .u64 t; cvta.to.shared.u64 t, %1; cvt.u32.u64 %0, t; }" : "=r"(a) : "l"(p));
    return a;
}
__device__ __forceinline__ void cp_async16(uint32_t dst, const void* src) {
    asm volatile("cp.async.ca.shared.global [%0], [%1], 16;" :: "r"(dst), "l"(src));
}
#define CP_COMMIT()   asm volatile("cp.async.commit_group;" ::: "memory")
#define CP_WAIT_ALL() asm volatile("cp.async.wait_all;" ::: "memory")
#define CP_WAIT0()    asm volatile("cp.async.wait_group 0;" ::: "memory")

__device__ __forceinline__ void mma_f16(float* c, const uint32_t* a, uint32_t b0, uint32_t b1) {
    asm volatile("mma.sync.aligned.m16n8k16.row.col.f32.f16.f16.f32 "
        "{%0,%1,%2,%3}, {%4,%5,%6,%7}, {%8,%9}, {%0,%1,%2,%3};"
        : "+f"(c[0]), "+f"(c[1]), "+f"(c[2]), "+f"(c[3])
        : "r"(a[0]), "r"(a[1]), "r"(a[2]), "r"(a[3]), "r"(b0), "r"(b1));
}
__device__ __forceinline__ void ldsm4(uint32_t* r, uint32_t addr) {
    asm volatile("ldmatrix.sync.aligned.m8n8.x4.shared.b16 {%0,%1,%2,%3}, [%4];"
        : "=r"(r[0]), "=r"(r[1]), "=r"(r[2]), "=r"(r[3]) : "r"(addr));
}
__device__ __forceinline__ float qgelu(float x) { return x / (1.f + __expf(-1.702f * x)); }

// ---------------- pool ----------------
__global__ void pool_kernel(const float* __restrict__ feat) {
    int bct = blockIdx.x;
    const float* p = feat + (size_t)bct * HW_;
    float s = 0.f;
    for (int i = threadIdx.x; i < HW_; i += blockDim.x) s += p[i];
    for (int o = 16; o; o >>= 1) s += __shfl_down_sync(0xffffffffu, s, o);
    __shared__ float sb[8];
    int lane = threadIdx.x & 31, w = threadIdx.x >> 5;
    if (lane == 0) sb[w] = s;
    __syncthreads();
    if (threadIdx.x == 0) {
        float t = 0.f;
        for (int i = 0; i < (int)(blockDim.x >> 5); i++) t += sb[i];
        g_pool[bct] = t * (1.f / HW_);
    }
}

// ---------------- routing + weight-prepack + stats-zero (fused grid) ----------------
__global__ void routing_fused_kernel(
    const float* __restrict__ a_w, const float* __restrict__ a_b,
    const float* __restrict__ norm_w, const float* __restrict__ norm_b,
    const float* __restrict__ normt_w, const float* __restrict__ normt_b,
    const float* __restrict__ qkv_w, const float* __restrict__ qkv_b,
    const float* __restrict__ ao_w, const float* __restrict__ ao_b,
    const float* __restrict__ b_w, const float* __restrict__ bb_w,
    const float* __restrict__ Wt)
{
    int tid = threadIdx.x;
    if (blockIdx.x >= B_) {
        int pb = blockIdx.x - B_;
        if (pb == 0) {
            for (int i = tid; i < C_*4; i += 256) ((double*)g_stats)[i] = 0.0;
        }
        int idx = pb * 256 + tid;           // < 589824
        int cc = idx & 31, o = (idx >> 5) & 255, kc = (idx >> 13) & 7, tap = idx >> 16;
        int ky = tap / 3, kx = tap % 3;
        g_wp[idx] = __float2half_rn(Wt[(((size_t)o*C_ + kc*32 + cc)*3 + ky)*3 + kx]);
        return;
    }
    int b = blockIdx.x;
    __shared__ float s_pool[C_][T_], s_x1[CR_][T_], s_x2[CR_][T_], s_xn[CR_][T_];
    __shared__ float s_qkv[3*CR_][T_], s_att[T_][T_], s_o[CR_][T_], s_mu[T_], s_rstd[T_];

    for (int i = tid; i < C_*T_; i += 256) s_pool[i >> 3][i & 7] = g_pool[b*C_*T_ + i];
    __syncthreads();
    for (int idx = tid; idx < CR_*T_; idx += 256) {
        int r = idx >> 3, t = idx & 7;
        float acc = a_b[r];
        const float* wb = a_w + (size_t)r * C_ * 3;
        for (int c = 0; c < C_; c++) {
            float p0 = (t > 0) ? s_pool[c][t-1] : 0.f, p1 = s_pool[c][t], p2 = (t < 7) ? s_pool[c][t+1] : 0.f;
            const float* w = wb + c*3;
            acc += w[0]*p0 + w[1]*p1 + w[2]*p2;
        }
        s_x1[r][t] = acc;
    }
    __syncthreads();
    if (tid < T_) {
        int t = tid;
        float mu = 0.f;
        for (int r = 0; r < CR_; r++) mu += s_x1[r][t];
        mu *= (1.f / CR_);
        float v = 0.f;
        for (int r = 0; r < CR_; r++) { float d = s_x1[r][t] - mu; v += d*d; }
        s_mu[t] = mu; s_rstd[t] = rsqrtf(v * (1.f / CR_) + 1e-6f);
    }
    __syncthreads();
    for (int idx = tid; idx < CR_*T_; idx += 256) {
        int r = idx >> 3, t = idx & 7;
        s_x2[r][t] = qgelu((s_x1[r][t] - s_mu[t]) * s_rstd[t] * norm_w[r] + norm_b[r]);
    }
    __syncthreads();
    if (tid < T_) {
        int t = tid;
        float mu = 0.f;
        for (int r = 0; r < CR_; r++) mu += s_x2[r][t];
        mu *= (1.f / CR_);
        float v = 0.f;
        for (int r = 0; r < CR_; r++) { float d = s_x2[r][t] - mu; v += d*d; }
        s_mu[t] = mu; s_rstd[t] = rsqrtf(v * (1.f / CR_) + 1e-6f);
    }
    __syncthreads();
    for (int idx = tid; idx < CR_*T_; idx += 256) {
        int r = idx >> 3, t = idx & 7;
        s_xn[r][t] = (s_x2[r][t] - s_mu[t]) * s_rstd[t] * normt_w[r] + normt_b[r];
    }
    __syncthreads();
    for (int idx = tid; idx < 3*CR_*T_; idx += 256) {
        int o = idx >> 3, t = idx & 7;
        float acc = qkv_b[o];
        const float* w = qkv_w + (size_t)o * CR_;
        for (int c = 0; c < CR_; c++) acc += w[c] * s_xn[c][t];
        s_qkv[o][t] = acc;
    }
    __syncthreads();
    if (tid < T_*T_) {
        int i = tid >> 3, j = tid & 7;
        float a = 0.f;
        for (int d = 0; d < CR_; d++) a += s_qkv[d][i] * s_qkv[CR_ + d][j];
        s_att[i][j] = a * 0.125f;
    }
    __syncthreads();
    if (tid < T_) {
        int i = tid;
        float m = -1e30f;
        for (int j = 0; j < T_; j++) m = fmaxf(m, s_att[i][j]);
        float sum = 0.f;
        for (int j = 0; j < T_; j++) { float e = __expf(s_att[i][j] - m); s_att[i][j] = e; sum += e; }
        float inv = 1.f / sum;
        for (int j = 0; j < T_; j++) s_att[i][j] *= inv;
    }
    __syncthreads();
    for (int idx = tid; idx < CR_*T_; idx += 256) {
        int d = idx >> 3, t = idx & 7;
        float a = 0.f;
        for (int j = 0; j < T_; j++) a += s_att[t][j] * s_qkv[2*CR_ + d][j];
        s_o[d][t] = a;
    }
    __syncthreads();
    for (int idx = tid; idx < CR_*T_; idx += 256) {
        int r = idx >> 3, t = idx & 7;
        float acc = ao_b[r];
        const float* w = ao_w + (size_t)r * CR_;
        for (int c = 0; c < CR_; c++) acc += w[c] * s_o[c][t];
        s_x1[r][t] = s_x2[r][t] + acc;
    }
    __syncthreads();
    for (int idx = tid; idx < C_*T_; idx += 256) {
        int Co = idx >> 3, t = idx & 7;
        float aw = 0.f, ab = 0.f;
        const float* w1b = b_w  + (size_t)Co * CR_ * 3;
        const float* w2b = bb_w + (size_t)Co * CR_ * 3;
        for (int r = 0; r < CR_; r++) {
            float x0 = (t > 0) ? s_x1[r][t-1] : 0.f, x1 = s_x1[r][t], x2 = (t < 7) ? s_x1[r][t+1] : 0.f;
            const float* w1 = w1b + r*3;
            const float* w2 = w2b + r*3;
            aw += w1[0]*x0 + w1[1]*x1 + w1[2]*x2;
            ab += w2[0]*x0 + w2[1]*x1 + w2[2]*x2;
        }
        g_walpha[b*C_*T_ + idx] = aw;
        g_balpha[b*C_*T_ + idx] = ab;
    }
}

// ---- stage scaled input -> padded NHWC fp16 ----
__global__ void stage_xs_kernel(const float* __restrict__ feat) {
    __shared__ float s[32][65];
    int img = blockIdx.z, r = blockIdx.y, c0 = blockIdx.x * 32;
    int b = img >> 3, t = img & 7;
    int tid = threadIdx.x;
    int x = tid & 63, cl0 = tid >> 6;
    for (int cl = cl0; cl < 32; cl += 4) {
        float v = 0.f;
        if (r >= 1 && r <= 56 && x >= 1 && x <= 56) {
            int c = c0 + cl;
            v = feat[(((size_t)(b*C_ + c))*T_ + t)*HW_ + (r-1)*W_ + (x-1)] * g_walpha[(b*C_ + c)*T_ + t];
        }
        s[cl][x] = v;
    }
    __syncthreads();
    int k = tid & 31, x0 = tid >> 5;
    for (int xx = x0; xx < 64; xx += 8)
        g_xs[((size_t)img*PXI_ + r*PC_ + xx)*C_ + c0 + k] = __float2half_rn(s[k][xx]);
}

// ---------------- conv: implicit GEMM fp16; kc=64 (36 iters), 4 warps, 2 CTAs/SM ----------------
__global__ void __launch_bounds__(128, 2)
conv_mma_kernel(const float* __restrict__ bias_p)
{
    extern __shared__ char smc[];
    float*  bias_sm = (float*)smc;            // 128 floats
    __half* As = (__half*)(smc + 1024);       // 2 x ABUFH halves
    __half* Bs = As + 2*ABUFH;                // 2 x BBUFH halves (ping-pong)
    uint32_t as_u = smem_to_u32(As);
    uint32_t bs_u = smem_to_u32(Bs);

    int tid = threadIdx.x, lane = tid & 31, wid = tid >> 5;
    int wm = wid >> 1, wn = wid & 1;          // warps 2(M=64) x 2(N=64)
    int mg = lane >> 2, tg = lane & 3;
    int img = blockIdx.z, bn = blockIdx.y, yt = blockIdx.x;
    int b = img >> 3, t = img & 7;
    size_t imgP = (size_t)img * PXI_ + (size_t)yt * 128;

    // per-lane ldmatrix address offsets (bytes), pitch APH=72 halves (144B)
    uint32_t aoff_l = (uint32_t)((((lane & 7) + (lane & 8)) * APH + ((lane & 16) >> 1)) * 2);
    uint32_t boff_l = (uint32_t)((((lane & 7) + ((lane & 16) >> 1)) * APH + (lane & 8)) * 2);

    bias_sm[tid] = g_balpha[(b*C_ + bn*128 + tid)*T_ + t] * bias_p[bn*128 + tid];

    // preload A(kc64=0): 258 rows x 64 ch, and B(iter 0) -> buf0
    const __half* srcA0 = g_xs + imgP*C_;
    for (int idx = tid; idx < 258*8; idx += 128) {
        int p = idx >> 3, q = idx & 7;
        cp_async16(as_u + (uint32_t)(p*144 + q*16), srcA0 + (size_t)p*C_ + q*8);
    }
    for (int idx = tid; idx < 1024; idx += 128) {
        int o = idx >> 3, q = idx & 7, chunk = q >> 2;
        cp_async16(bs_u + (uint32_t)(o*144 + q*16),
                   g_wp + ((size_t)(0*8 + 0 + chunk)*256 + bn*128 + o)*32 + (q & 3)*8);
    }
    CP_COMMIT(); CP_WAIT_ALL();
    __syncthreads();

    float acc[4][8][4] = {};

    for (int tt = 0; tt < 36; tt++) {
        int kc = tt / 9, tap = tt % 9;
        if (tt > 0) { CP_WAIT0(); __syncthreads(); }   // B(tt)+A slices visible; prev reads done

        bool committed = false;
        if (tt + 1 < 36) {        // stage B(tt+1) into other buffer
            int n = tt + 1, nk = n / 9, nt = n % 9;
            uint32_t dstb = bs_u + (uint32_t)(n & 1)*(BBUFH*2);
            for (int idx = tid; idx < 1024; idx += 128) {
                int o = idx >> 3, q = idx & 7, chunk = q >> 2;
                cp_async16(dstb + (uint32_t)(o*144 + q*16),
                           g_wp + ((size_t)(nt*8 + nk*2 + chunk)*256 + bn*128 + o)*32 + (q & 3)*8);
            }
            committed = true;
        }
        if (kc < 3 && tap < 8) {  // stage a slice of A(kc+1)
            const __half* srcAn = g_xs + imgP*C_ + (size_t)(kc+1)*64;
            uint32_t dsta = as_u + (uint32_t)(((kc+1) & 1)*(ABUFH*2));
            int r0 = tap*33, r1 = min(r0 + 33, 258);
            for (int idx = tid + r0*8; idx < r1*8; idx += 128) {
                int p = idx >> 3, q = idx & 7;
                cp_async16(dsta + (uint32_t)(p*144 + q*16), srcAn + (size_t)p*C_ + q*8);
            }
            committed = true;
        }
        if (committed) CP_COMMIT();

        int off = (tap/3)*64 + (tap%3);
        uint32_t abase = as_u + (uint32_t)((kc & 1)*(ABUFH*2)) + (uint32_t)((off + wm*64)*144) + aoff_l;
        uint32_t bbase = bs_u + (uint32_t)((tt & 1)*(BBUFH*2)) + (uint32_t)((wn*64)*144) + boff_l;
        #pragma unroll
        for (int ks = 0; ks < 4; ks++) {
            uint32_t af[4][4];
            #pragma unroll
            for (int i = 0; i < 4; i++)
                ldsm4(af[i], abase + (uint32_t)(i*16*144 + ks*32));
            #pragma unroll
            for (int jp = 0; jp < 4; jp++) {
                uint32_t bf[4];
                ldsm4(bf, bbase + (uint32_t)(jp*16*144 + ks*32));
                #pragma unroll
                for (int i = 0; i < 4; i++) {
                    mma_f16(acc[i][2*jp],   af[i], bf[0], bf[1]);
                    mma_f16(acc[i][2*jp+1], af[i], bf[2], bf[3]);
                }
            }
        }
    }
    __syncthreads();   // protect smem reuse by epilogue

    // epilogue: transpose through smem (64 ch at a time), coalesced float4 stores
    float* ep = (float*)(smc + 1024);   // 64 x EPS floats = 33.8KB (fits in A region)
    #pragma unroll
    for (int h = 0; h < 2; h++) {
        if (wn == h) {
            #pragma unroll
            for (int i = 0; i < 4; i++)
                #pragma unroll
                for (int j = 0; j < 8; j++)
                    #pragma unroll
                    for (int e = 0; e < 4; e++) {
                        int nl = j*8 + tg*2 + (e & 1);                 // 0..63
                        int m  = wm*64 + i*16 + mg + ((e >> 1)*8);     // 0..127
                        ep[nl*EPS + m] = acc[i][j][e] + bias_sm[h*64 + nl];
                    }
        }
        __syncthreads();
        int sub = lane >> 4, xi = lane & 15;
        #pragma unroll
        for (int it = 0; it < 16; it++) {
            int rowIdx = it*8 + wid*2 + sub;   // 0..127 = ch(64) x ry(2)
            int ch = rowIdx >> 1, ry = rowIdx & 1;
            if (xi < 14) {
                float4 v = *(const float4*)&ep[ch*EPS + ry*64 + xi*4];
                int o = bn*128 + h*64 + ch;
                *(float4*)&g_conv[(((size_t)(b*C_ + o))*T_ + t)*HW_ + (yt*2 + ry)*W_ + xi*4] = v;
            }
        }
        __syncthreads();
    }
}

// ---------------- stats + coef + final ----------------
__global__ void stats_kernel() {
    int c = blockIdx.y;
    int item = blockIdx.x * blockDim.x + threadIdx.x;
    int b = item / HW_, hw = item % HW_;
    size_t base = (((size_t)b*C_ + c)*T_) * HW_ + hw;
    float so = 0.f, sq = 0.f, sa = 0.f, sqa = 0.f, prev = 0.f, cur = g_conv[base];
    #pragma unroll
    for (int t = 0; t < T_; t++) {
        float nxt = (t < T_-1) ? g_conv[base + (size_t)(t+1)*HW_] : 0.f;
        so += cur; sq += cur*cur;
        float ap = (prev + cur + nxt) * (1.f/3.f);
        sa += ap; sqa += ap*ap;
        prev = cur; cur = nxt;
    }
    __shared__ float sb[4][8];
    for (int o = 16; o; o >>= 1) {
        so += __shfl_down_sync(0xffffffffu, so, o);
        sq += __shfl_down_sync(0xffffffffu, sq, o);
        sa += __shfl_down_sync(0xffffffffu, sa, o);
        sqa += __shfl_down_sync(0xffffffffu, sqa, o);
    }
    int lane = threadIdx.x & 31, w = threadIdx.x >> 5;
    if (lane == 0) { sb[0][w] = so; sb[1][w] = sq; sb[2][w] = sa; sb[3][w] = sqa; }
    __syncthreads();
    if (threadIdx.x == 0) {
        float a0=0, a1=0, a2=0, a3=0;
        for (int i = 0; i < 8; i++) { a0+=sb[0][i]; a1+=sb[1][i]; a2+=sb[2][i]; a3+=sb[3][i]; }
        atomicAdd(&g_stats[c][0], (double)a0);
        atomicAdd(&g_stats[c][1], (double)a1);
        atomicAdd(&g_stats[c][2], (double)a2);
        atomicAdd(&g_stats[c][3], (double)a3);
    }
}
__global__ void coef_kernel(const float* __restrict__ gamma_a, const float* __restrict__ beta_a,
                            const float* __restrict__ gamma_b, const float* __restrict__ beta_b)
{
    int c = threadIdx.x;
    const double N = (double)B_ * T_ * HW_;
    double mu_a = g_stats[c][0] / N, va = g_stats[c][1] / N - mu_a*mu_a;
    double mu_b = g_stats[c][2] / N, vb = g_stats[c][3] / N - mu_b*mu_b;
    float sca = gamma_a[c] * (float)(1.0 / sqrt(va + 1e-5));
    float sha = beta_a[c] - (float)mu_a * sca;
    float scb = gamma_b[c] * (float)(1.0 / sqrt(vb + 1e-5));
    float shb = beta_b[c] - (float)mu_b * scb;
    g_coef[c] = make_float4(sca, sha, scb, shb);
}
__global__ void final_kernel(float* __restrict__ out)
{
    int c = blockIdx.y;
    int item = blockIdx.x * blockDim.x + threadIdx.x;
    int b = item / HW_, hw = item % HW_;
    float4 cf = g_coef[c];
    size_t base = (((size_t)b*C_ + c)*T_) * HW_ + hw;
    float prev = 0.f, cur = g_conv[base];
    #pragma unroll
    for (int t = 0; t < T_; t++) {
        float nxt = (t < T_-1) ? g_conv[base + (size_t)(t+1)*HW_] : 0.f;
        float ap = (prev + cur + nxt) * (1.f/3.f);
        out[base + (size_t)t*HW_] = cur*cf.x + cf.y + ap*cf.z + cf.w;
        prev = cur; cur = nxt;
    }
}

// ---------------------------------------------------------------------------
extern "C" void kernel_launch(void* const* d_in, const int* in_sizes, int n_in,
                              void* d_out, int out_size)
{
    const float* feat    = (const float*)d_in[0];
    const float* Wt      = (const float*)d_in[1];
    const float* bias_p  = (const float*)d_in[2];
    const float* a_w     = (const float*)d_in[3];
    const float* a_b     = (const float*)d_in[4];
    const float* norm_w  = (const float*)d_in[5];
    const float* norm_b  = (const float*)d_in[6];
    const float* normt_w = (const float*)d_in[7];
    const float* normt_b = (const float*)d_in[8];
    const float* qkv_w   = (const float*)d_in[9];
    const float* qkv_b   = (const float*)d_in[10];
    const float* ao_w    = (const float*)d_in[11];
    const float* ao_b    = (const float*)d_in[12];
    const float* b_w     = (const float*)d_in[13];
    const float* bb_w    = (const float*)d_in[14];
    const float* gamma_a = (const float*)d_in[15];
    const float* beta_a  = (const float*)d_in[16];
    const float* gamma_b = (const float*)d_in[17];
    const float* beta_b  = (const float*)d_in[18];
    float* out = (float*)d_out;

    cudaFuncSetAttribute(conv_mma_kernel, cudaFuncAttributeMaxDynamicSharedMemorySize, SMEM_BYTES);

    pool_kernel<<<B_*C_*T_, 128>>>(feat);                               // launch 1
    routing_fused_kernel<<<B_ + 2304, 256>>>(a_w, a_b, norm_w, norm_b,  // launch 2
        normt_w, normt_b, qkv_w, qkv_b, ao_w, ao_b, b_w, bb_w, Wt);
    stage_xs_kernel<<<dim3(8, PR_, NIMG), 256>>>(feat);                 // launch 3
    conv_mma_kernel<<<dim3(28, 2, NIMG), 128, SMEM_BYTES>>>(bias_p);    // launch 4 (profiled)
    stats_kernel<<<dim3(98, 256), 256>>>();                             // launch 5
    coef_kernel<<<1, 256>>>(gamma_a, beta_a, gamma_b, beta_b);          // launch 6
    final_kernel<<<dim3(98, 256), 256>>>(out);                          // launch 7
}

// round 16
// speedup vs baseline: 1.9627x; 1.0433x over previous
#include <cuda_runtime.h>
#include <cuda_fp16.h>
#include <math.h>
#include <stdint.h>

#define B_  8
#define C_  256
#define T_  8
#define H_  56
#define W_  56
#define HW_ (H_*W_)
#define CR_ 64
#define PR_ 58
#define PC_ 64
#define PXI_ (PR_*PC_)     // 3712
#define NIMG 64
#define APH 72             // smem row pitch in halves (144B) — LDSM conflict-free
#define ABUFH (258*APH)
#define BBUFH (128*APH)
#define EPS 132
#define SMEM_BYTES (1024 + 2*ABUFH*2 + 2*BBUFH*2)   // 112192

__device__ float  g_pool[B_*C_*T_];
__device__ float  g_walpha[B_*C_*T_];
__device__ float  g_balpha[B_*C_*T_];
__device__ __half g_conv[(size_t)B_*C_*T_*HW_];      // fp16 pre-BN conv output
__device__ double g_stats[C_][4];
__device__ float4 g_coef[C_];
__device__ __half g_xs[(size_t)NIMG*PXI_*C_ + 4096]; // padded NHWC fp16 (+OOB guard)
__device__ __half g_wp[9*8*256*32];                  // [tap][kc32][o][cc] fp16

// ---------------- helpers ----------------
__device__ __forceinline__ uint32_t smem_to_u32(const void* p) {
    uint32_t a;
    asm("{ .reg .u64 t; cvta.to.shared.u64 t, %1; cvt.u32.u64 %0, t; }" : "=r"(a) : "l"(p));
    return a;
}
__device__ __forceinline__ void cp_async16(uint32_t dst, const void* src) {
    asm volatile("cp.async.ca.shared.global [%0], [%1], 16;" :: "r"(dst), "l"(src));
}
#define CP_COMMIT()   asm volatile("cp.async.commit_group;" ::: "memory")
#define CP_WAIT_ALL() asm volatile("cp.async.wait_all;" ::: "memory")
#define CP_WAIT0()    asm volatile("cp.async.wait_group 0;" ::: "memory")

__device__ __forceinline__ void mma_f16(float* c, const uint32_t* a, uint32_t b0, uint32_t b1) {
    asm volatile("mma.sync.aligned.m16n8k16.row.col.f32.f16.f16.f32 "
        "{%0,%1,%2,%3}, {%4,%5,%6,%7}, {%8,%9}, {%0,%1,%2,%3};"
        : "+f"(c[0]), "+f"(c[1]), "+f"(c[2]), "+f"(c[3])
        : "r"(a[0]), "r"(a[1]), "r"(a[2]), "r"(a[3]), "r"(b0), "r"(b1));
}
__device__ __forceinline__ void ldsm4(uint32_t* r, uint32_t addr) {
    asm volatile("ldmatrix.sync.aligned.m8n8.x4.shared.b16 {%0,%1,%2,%3}, [%4];"
        : "=r"(r[0]), "=r"(r[1]), "=r"(r[2]), "=r"(r[3]) : "r"(addr));
}
__device__ __forceinline__ float qgelu(float x) { return x / (1.f + __expf(-1.702f * x)); }

// ---------------- pool (float4 reads) ----------------
__global__ void pool_kernel(const float* __restrict__ feat) {
    int bct = blockIdx.x;
    const float4* p = (const float4*)(feat + (size_t)bct * HW_);
    float s = 0.f;
    for (int i = threadIdx.x; i < HW_/4; i += blockDim.x) {
        float4 v = p[i];
        s += (v.x + v.y) + (v.z + v.w);
    }
    for (int o = 16; o; o >>= 1) s += __shfl_down_sync(0xffffffffu, s, o);
    __shared__ float sb[8];
    int lane = threadIdx.x & 31, w = threadIdx.x >> 5;
    if (lane == 0) sb[w] = s;
    __syncthreads();
    if (threadIdx.x == 0) {
        float t = 0.f;
        for (int i = 0; i < (int)(blockDim.x >> 5); i++) t += sb[i];
        g_pool[bct] = t * (1.f / HW_);
    }
}

// ---------------- routing + weight-prepack + stats-zero (fused grid) ----------------
__global__ void routing_fused_kernel(
    const float* __restrict__ a_w, const float* __restrict__ a_b,
    const float* __restrict__ norm_w, const float* __restrict__ norm_b,
    const float* __restrict__ normt_w, const float* __restrict__ normt_b,
    const float* __restrict__ qkv_w, const float* __restrict__ qkv_b,
    const float* __restrict__ ao_w, const float* __restrict__ ao_b,
    const float* __restrict__ b_w, const float* __restrict__ bb_w,
    const float* __restrict__ Wt)
{
    int tid = threadIdx.x;
    if (blockIdx.x >= B_) {
        int pb = blockIdx.x - B_;
        if (pb == 0) {
            for (int i = tid; i < C_*4; i += 256) ((double*)g_stats)[i] = 0.0;
        }
        int idx = pb * 256 + tid;           // < 589824
        int cc = idx & 31, o = (idx >> 5) & 255, kc = (idx >> 13) & 7, tap = idx >> 16;
        int ky = tap / 3, kx = tap % 3;
        g_wp[idx] = __float2half_rn(Wt[(((size_t)o*C_ + kc*32 + cc)*3 + ky)*3 + kx]);
        return;
    }
    int b = blockIdx.x;
    __shared__ float s_pool[C_][T_], s_x1[CR_][T_], s_x2[CR_][T_], s_xn[CR_][T_];
    __shared__ float s_qkv[3*CR_][T_], s_att[T_][T_], s_o[CR_][T_], s_mu[T_], s_rstd[T_];

    for (int i = tid; i < C_*T_; i += 256) s_pool[i >> 3][i & 7] = g_pool[b*C_*T_ + i];
    __syncthreads();
    for (int idx = tid; idx < CR_*T_; idx += 256) {
        int r = idx >> 3, t = idx & 7;
        float acc = a_b[r];
        const float* wb = a_w + (size_t)r * C_ * 3;
        for (int c = 0; c < C_; c++) {
            float p0 = (t > 0) ? s_pool[c][t-1] : 0.f, p1 = s_pool[c][t], p2 = (t < 7) ? s_pool[c][t+1] : 0.f;
            const float* w = wb + c*3;
            acc += w[0]*p0 + w[1]*p1 + w[2]*p2;
        }
        s_x1[r][t] = acc;
    }
    __syncthreads();
    if (tid < T_) {
        int t = tid;
        float mu = 0.f;
        for (int r = 0; r < CR_; r++) mu += s_x1[r][t];
        mu *= (1.f / CR_);
        float v = 0.f;
        for (int r = 0; r < CR_; r++) { float d = s_x1[r][t] - mu; v += d*d; }
        s_mu[t] = mu; s_rstd[t] = rsqrtf(v * (1.f / CR_) + 1e-6f);
    }
    __syncthreads();
    for (int idx = tid; idx < CR_*T_; idx += 256) {
        int r = idx >> 3, t = idx & 7;
        s_x2[r][t] = qgelu((s_x1[r][t] - s_mu[t]) * s_rstd[t] * norm_w[r] + norm_b[r]);
    }
    __syncthreads();
    if (tid < T_) {
        int t = tid;
        float mu = 0.f;
        for (int r = 0; r < CR_; r++) mu += s_x2[r][t];
        mu *= (1.f / CR_);
        float v = 0.f;
        for (int r = 0; r < CR_; r++) { float d = s_x2[r][t] - mu; v += d*d; }
        s_mu[t] = mu; s_rstd[t] = rsqrtf(v * (1.f / CR_) + 1e-6f);
    }
    __syncthreads();
    for (int idx = tid; idx < CR_*T_; idx += 256) {
        int r = idx >> 3, t = idx & 7;
        s_xn[r][t] = (s_x2[r][t] - s_mu[t]) * s_rstd[t] * normt_w[r] + normt_b[r];
    }
    __syncthreads();
    for (int idx = tid; idx < 3*CR_*T_; idx += 256) {
        int o = idx >> 3, t = idx & 7;
        float acc = qkv_b[o];
        const float* w = qkv_w + (size_t)o * CR_;
        for (int c = 0; c < CR_; c++) acc += w[c] * s_xn[c][t];
        s_qkv[o][t] = acc;
    }
    __syncthreads();
    if (tid < T_*T_) {
        int i = tid >> 3, j = tid & 7;
        float a = 0.f;
        for (int d = 0; d < CR_; d++) a += s_qkv[d][i] * s_qkv[CR_ + d][j];
        s_att[i][j] = a * 0.125f;
    }
    __syncthreads();
    if (tid < T_) {
        int i = tid;
        float m = -1e30f;
        for (int j = 0; j < T_; j++) m = fmaxf(m, s_att[i][j]);
        float sum = 0.f;
        for (int j = 0; j < T_; j++) { float e = __expf(s_att[i][j] - m); s_att[i][j] = e; sum += e; }
        float inv = 1.f / sum;
        for (int j = 0; j < T_; j++) s_att[i][j] *= inv;
    }
    __syncthreads();
    for (int idx = tid; idx < CR_*T_; idx += 256) {
        int d = idx >> 3, t = idx & 7;
        float a = 0.f;
        for (int j = 0; j < T_; j++) a += s_att[t][j] * s_qkv[2*CR_ + d][j];
        s_o[d][t] = a;
    }
    __syncthreads();
    for (int idx = tid; idx < CR_*T_; idx += 256) {
        int r = idx >> 3, t = idx & 7;
        float acc = ao_b[r];
        const float* w = ao_w + (size_t)r * CR_;
        for (int c = 0; c < CR_; c++) acc += w[c] * s_o[c][t];
        s_x1[r][t] = s_x2[r][t] + acc;
    }
    __syncthreads();
    for (int idx = tid; idx < C_*T_; idx += 256) {
        int Co = idx >> 3, t = idx & 7;
        float aw = 0.f, ab = 0.f;
        const float* w1b = b_w  + (size_t)Co * CR_ * 3;
        const float* w2b = bb_w + (size_t)Co * CR_ * 3;
        for (int r = 0; r < CR_; r++) {
            float x0 = (t > 0) ? s_x1[r][t-1] : 0.f, x1 = s_x1[r][t], x2 = (t < 7) ? s_x1[r][t+1] : 0.f;
            const float* w1 = w1b + r*3;
            const float* w2 = w2b + r*3;
            aw += w1[0]*x0 + w1[1]*x1 + w1[2]*x2;
            ab += w2[0]*x0 + w2[1]*x1 + w2[2]*x2;
        }
        g_walpha[b*C_*T_ + idx] = aw;
        g_balpha[b*C_*T_ + idx] = ab;
    }
}

// ---- stage scaled input -> padded NHWC fp16 ----
__global__ void stage_xs_kernel(const float* __restrict__ feat) {
    __shared__ float s[32][65];
    int img = blockIdx.z, r = blockIdx.y, c0 = blockIdx.x * 32;
    int b = img >> 3, t = img & 7;
    int tid = threadIdx.x;
    int x = tid & 63, cl0 = tid >> 6;
    for (int cl = cl0; cl < 32; cl += 4) {
        float v = 0.f;
        if (r >= 1 && r <= 56 && x >= 1 && x <= 56) {
            int c = c0 + cl;
            v = feat[(((size_t)(b*C_ + c))*T_ + t)*HW_ + (r-1)*W_ + (x-1)] * g_walpha[(b*C_ + c)*T_ + t];
        }
        s[cl][x] = v;
    }
    __syncthreads();
    int k = tid & 31, x0 = tid >> 5;
    for (int xx = x0; xx < 64; xx += 8)
        g_xs[((size_t)img*PXI_ + r*PC_ + xx)*C_ + c0 + k] = __float2half_rn(s[k][xx]);
}

// ---------------- conv: implicit GEMM fp16; kc=64 (36 iters), 4 warps, 2 CTAs/SM ----------------
__global__ void __launch_bounds__(128, 2)
conv_mma_kernel(const float* __restrict__ bias_p)
{
    extern __shared__ char smc[];
    float*  bias_sm = (float*)smc;            // 128 floats
    __half* As = (__half*)(smc + 1024);       // 2 x ABUFH halves
    __half* Bs = As + 2*ABUFH;                // 2 x BBUFH halves (ping-pong)
    uint32_t as_u = smem_to_u32(As);
    uint32_t bs_u = smem_to_u32(Bs);

    int tid = threadIdx.x, lane = tid & 31, wid = tid >> 5;
    int wm = wid >> 1, wn = wid & 1;          // warps 2(M=64) x 2(N=64)
    int mg = lane >> 2, tg = lane & 3;
    int img = blockIdx.z, bn = blockIdx.y, yt = blockIdx.x;
    int b = img >> 3, t = img & 7;
    size_t imgP = (size_t)img * PXI_ + (size_t)yt * 128;

    uint32_t aoff_l = (uint32_t)((((lane & 7) + (lane & 8)) * APH + ((lane & 16) >> 1)) * 2);
    uint32_t boff_l = (uint32_t)((((lane & 7) + ((lane & 16) >> 1)) * APH + (lane & 8)) * 2);

    bias_sm[tid] = g_balpha[(b*C_ + bn*128 + tid)*T_ + t] * bias_p[bn*128 + tid];

    const __half* srcA0 = g_xs + imgP*C_;
    for (int idx = tid; idx < 258*8; idx += 128) {
        int p = idx >> 3, q = idx & 7;
        cp_async16(as_u + (uint32_t)(p*144 + q*16), srcA0 + (size_t)p*C_ + q*8);
    }
    for (int idx = tid; idx < 1024; idx += 128) {
        int o = idx >> 3, q = idx & 7, chunk = q >> 2;
        cp_async16(bs_u + (uint32_t)(o*144 + q*16),
                   g_wp + ((size_t)(0*8 + 0 + chunk)*256 + bn*128 + o)*32 + (q & 3)*8);
    }
    CP_COMMIT(); CP_WAIT_ALL();
    __syncthreads();

    float acc[4][8][4] = {};

    for (int tt = 0; tt < 36; tt++) {
        int kc = tt / 9, tap = tt % 9;
        if (tt > 0) { CP_WAIT0(); __syncthreads(); }

        bool committed = false;
        if (tt + 1 < 36) {
            int n = tt + 1, nk = n / 9, nt = n % 9;
            uint32_t dstb = bs_u + (uint32_t)(n & 1)*(BBUFH*2);
            for (int idx = tid; idx < 1024; idx += 128) {
                int o = idx >> 3, q = idx & 7, chunk = q >> 2;
                cp_async16(dstb + (uint32_t)(o*144 + q*16),
                           g_wp + ((size_t)(nt*8 + nk*2 + chunk)*256 + bn*128 + o)*32 + (q & 3)*8);
            }
            committed = true;
        }
        if (kc < 3 && tap < 8) {
            const __half* srcAn = g_xs + imgP*C_ + (size_t)(kc+1)*64;
            uint32_t dsta = as_u + (uint32_t)(((kc+1) & 1)*(ABUFH*2));
            int r0 = tap*33, r1 = min(r0 + 33, 258);
            for (int idx = tid + r0*8; idx < r1*8; idx += 128) {
                int p = idx >> 3, q = idx & 7;
                cp_async16(dsta + (uint32_t)(p*144 + q*16), srcAn + (size_t)p*C_ + q*8);
            }
            committed = true;
        }
        if (committed) CP_COMMIT();

        int off = (tap/3)*64 + (tap%3);
        uint32_t abase = as_u + (uint32_t)((kc & 1)*(ABUFH*2)) + (uint32_t)((off + wm*64)*144) + aoff_l;
        uint32_t bbase = bs_u + (uint32_t)((tt & 1)*(BBUFH*2)) + (uint32_t)((wn*64)*144) + boff_l;
        #pragma unroll
        for (int ks = 0; ks < 4; ks++) {
            uint32_t af[4][4];
            #pragma unroll
            for (int i = 0; i < 4; i++)
                ldsm4(af[i], abase + (uint32_t)(i*16*144 + ks*32));
            #pragma unroll
            for (int jp = 0; jp < 4; jp++) {
                uint32_t bf[4];
                ldsm4(bf, bbase + (uint32_t)(jp*16*144 + ks*32));
                #pragma unroll
                for (int i = 0; i < 4; i++) {
                    mma_f16(acc[i][2*jp],   af[i], bf[0], bf[1]);
                    mma_f16(acc[i][2*jp+1], af[i], bf[2], bf[3]);
                }
            }
        }
    }
    __syncthreads();   // protect smem reuse by epilogue

    // epilogue: transpose through smem, half2-packed coalesced stores
    float* ep = (float*)(smc + 1024);   // 64 x EPS floats
    #pragma unroll
    for (int h = 0; h < 2; h++) {
        if (wn == h) {
            #pragma unroll
            for (int i = 0; i < 4; i++)
                #pragma unroll
                for (int j = 0; j < 8; j++)
                    #pragma unroll
                    for (int e = 0; e < 4; e++) {
                        int nl = j*8 + tg*2 + (e & 1);                 // 0..63
                        int m  = wm*64 + i*16 + mg + ((e >> 1)*8);     // 0..127
                        ep[nl*EPS + m] = acc[i][j][e] + bias_sm[h*64 + nl];
                    }
        }
        __syncthreads();
        int sub = lane >> 4, xi = lane & 15;
        #pragma unroll
        for (int it = 0; it < 16; it++) {
            int rowIdx = it*8 + wid*2 + sub;   // 0..127 = ch(64) x ry(2)
            int ch = rowIdx >> 1, ry = rowIdx & 1;
            if (xi < 14) {
                float4 v = *(const float4*)&ep[ch*EPS + ry*64 + xi*4];
                __half2 h0 = __floats2half2_rn(v.x, v.y);
                __half2 h1 = __floats2half2_rn(v.z, v.w);
                uint2 pk;
                pk.x = *(uint32_t*)&h0;
                pk.y = *(uint32_t*)&h1;
                int o = bn*128 + h*64 + ch;
                *(uint2*)&g_conv[(((size_t)(b*C_ + o))*T_ + t)*HW_ + (yt*2 + ry)*W_ + xi*4] = pk;
            }
        }
        __syncthreads();
    }
}

// ---------------- stats + coef + final (half2-pair processing) ----------------
__global__ void stats_kernel() {
    int c = blockIdx.y;
    int item = blockIdx.x * blockDim.x + threadIdx.x;   // 0..12543
    int b = item / (HW_/2), hp = item % (HW_/2);
    size_t base = (((size_t)b*C_ + c)*T_) * HW_ + hp*2;
    float so = 0.f, sq = 0.f, sa = 0.f, sqa = 0.f;
    float2 prev = make_float2(0.f, 0.f);
    float2 cur  = __half22float2(*(const __half2*)&g_conv[base]);
    #pragma unroll
    for (int t = 0; t < T_; t++) {
        float2 nxt = (t < T_-1) ? __half22float2(*(const __half2*)&g_conv[base + (size_t)(t+1)*HW_])
                                : make_float2(0.f, 0.f);
        so += cur.x + cur.y;
        sq += cur.x*cur.x + cur.y*cur.y;
        float apx = (prev.x + cur.x + nxt.x) * (1.f/3.f);
        float apy = (prev.y + cur.y + nxt.y) * (1.f/3.f);
        sa  += apx + apy;
        sqa += apx*apx + apy*apy;
        prev = cur; cur = nxt;
    }
    __shared__ float sb[4][8];
    for (int o = 16; o; o >>= 1) {
        so += __shfl_down_sync(0xffffffffu, so, o);
        sq += __shfl_down_sync(0xffffffffu, sq, o);
        sa += __shfl_down_sync(0xffffffffu, sa, o);
        sqa += __shfl_down_sync(0xffffffffu, sqa, o);
    }
    int lane = threadIdx.x & 31, w = threadIdx.x >> 5;
    if (lane == 0) { sb[0][w] = so; sb[1][w] = sq; sb[2][w] = sa; sb[3][w] = sqa; }
    __syncthreads();
    if (threadIdx.x == 0) {
        float a0=0, a1=0, a2=0, a3=0;
        for (int i = 0; i < 8; i++) { a0+=sb[0][i]; a1+=sb[1][i]; a2+=sb[2][i]; a3+=sb[3][i]; }
        atomicAdd(&g_stats[c][0], (double)a0);
        atomicAdd(&g_stats[c][1], (double)a1);
        atomicAdd(&g_stats[c][2], (double)a2);
        atomicAdd(&g_stats[c][3], (double)a3);
    }
}
__global__ void coef_kernel(const float* __restrict__ gamma_a, const float* __restrict__ beta_a,
                            const float* __restrict__ gamma_b, const float* __restrict__ beta_b)
{
    int c = threadIdx.x;
    const double N = (double)B_ * T_ * HW_;
    double mu_a = g_stats[c][0] / N, va = g_stats[c][1] / N - mu_a*mu_a;
    double mu_b = g_stats[c][2] / N, vb = g_stats[c][3] / N - mu_b*mu_b;
    float sca = gamma_a[c] * (float)(1.0 / sqrt(va + 1e-5));
    float sha = beta_a[c] - (float)mu_a * sca;
    float scb = gamma_b[c] * (float)(1.0 / sqrt(vb + 1e-5));
    float shb = beta_b[c] - (float)mu_b * scb;
    g_coef[c] = make_float4(sca, sha, scb, shb);
}
__global__ void final_kernel(float* __restrict__ out)
{
    int c = blockIdx.y;
    int item = blockIdx.x * blockDim.x + threadIdx.x;   // 0..12543
    int b = item / (HW_/2), hp = item % (HW_/2);
    float4 cf = g_coef[c];
    size_t base = (((size_t)b*C_ + c)*T_) * HW_ + hp*2;
    float2 prev = make_float2(0.f, 0.f);
    float2 cur  = __half22float2(*(const __half2*)&g_conv[base]);
    #pragma unroll
    for (int t = 0; t < T_; t++) {
        float2 nxt = (t < T_-1) ? __half22float2(*(const __half2*)&g_conv[base + (size_t)(t+1)*HW_])
                                : make_float2(0.f, 0.f);
        float apx = (prev.x + cur.x + nxt.x) * (1.f/3.f);
        float apy = (prev.y + cur.y + nxt.y) * (1.f/3.f);
        float2 o;
        o.x = cur.x*cf.x + cf.y + apx*cf.z + cf.w;
        o.y = cur.y*cf.x + cf.y + apy*cf.z + cf.w;
        *(float2*)&out[base + (size_t)t*HW_] = o;
        prev = cur; cur = nxt;
    }
}

// ---------------------------------------------------------------------------
extern "C" void kernel_launch(void* const* d_in, const int* in_sizes, int n_in,
                              void* d_out, int out_size)
{
    const float* feat    = (const float*)d_in[0];
    const float* Wt      = (const float*)d_in[1];
    const float* bias_p  = (const float*)d_in[2];
    const float* a_w     = (const float*)d_in[3];
    const float* a_b     = (const float*)d_in[4];
    const float* norm_w  = (const float*)d_in[5];
    const float* norm_b  = (const float*)d_in[6];
    const float* normt_w = (const float*)d_in[7];
    const float* normt_b = (const float*)d_in[8];
    const float* qkv_w   = (const float*)d_in[9];
    const float* qkv_b   = (const float*)d_in[10];
    const float* ao_w    = (const float*)d_in[11];
    const float* ao_b    = (const float*)d_in[12];
    const float* b_w     = (const float*)d_in[13];
    const float* bb_w    = (const float*)d_in[14];
    const float* gamma_a = (const float*)d_in[15];
    const float* beta_a  = (const float*)d_in[16];
    const float* gamma_b = (const float*)d_in[17];
    const float* beta_b  = (const float*)d_in[18];
    float* out = (float*)d_out;

    cudaFuncSetAttribute(conv_mma_kernel, cudaFuncAttributeMaxDynamicSharedMemorySize, SMEM_BYTES);

    pool_kernel<<<B_*C_*T_, 128>>>(feat);                               // launch 1
    routing_fused_kernel<<<B_ + 2304, 256>>>(a_w, a_b, norm_w, norm_b,  // launch 2
        normt_w, normt_b, qkv_w, qkv_b, ao_w, ao_b, b_w, bb_w, Wt);
    stage_xs_kernel<<<dim3(8, PR_, NIMG), 256>>>(feat);                 // launch 3
    conv_mma_kernel<<<dim3(28, 2, NIMG), 128, SMEM_BYTES>>>(bias_p);    // launch 4 (profiled)
    stats_kernel<<<dim3(49, 256), 256>>>();                             // launch 5
    coef_kernel<<<1, 256>>>(gamma_a, beta_a, gamma_b, beta_b);          // launch 6
    final_kernel<<<dim3(49, 256), 256>>>(out);                          // launch 7
}